// round 1
// baseline (speedup 1.0000x reference)
#include <cuda_runtime.h>
#include <cuda_bf16.h>
#include <math.h>

// ---------------- problem constants ----------------
#define LSEQ   2048
#define DM     768
#define DI     1536          // 2*DM
#define DXZ    3072          // 2*DI
#define DTR    48
#define DS     16
#define DCONV  4
#define NLAYER 2
#define XDBL   80            // DTR + 2*DS
#define NCH    16
#define CLEN   128           // LSEQ / NCH

// ---------------- scratch (device globals, no allocation) ----------------
__device__ float g_x   [LSEQ * DM];       // residual stream
__device__ float g_xn  [LSEQ * DM];       // rmsnorm output
__device__ float g_xz  [LSEQ * DXZ];      // in_proj output (xr | res)
__device__ float g_xr  [LSEQ * DI];       // conv+silu output
__device__ float g_xdbl[LSEQ * XDBL];     // x_proj output (dt | B | C)
__device__ float g_delta[LSEQ * DI];      // softplus(dt@dt_proj + b)
__device__ float g_ya  [LSEQ * DI];       // (y + u*D) * silu(res)
__device__ float g_Aprod[NCH * DI * DS];
__device__ float g_Hend [NCH * DI * DS];
__device__ float g_Hinit[NCH * DI * DS];

// ---------------- elementwise kernels ----------------
__global__ void embed_kernel(const int* __restrict__ ids,
                             const float* __restrict__ emb) {
    int i = blockIdx.x * blockDim.x + threadIdx.x;
    if (i >= LSEQ * DM) return;
    int l = i / DM, d = i - l * DM;
    g_x[i] = emb[(size_t)ids[l] * DM + d];
}

__global__ void rmsnorm_kernel(const float* __restrict__ w) {
    int l = blockIdx.x;
    const float* xr = &g_x[(size_t)l * DM];
    float s = 0.f;
    for (int d = threadIdx.x; d < DM; d += 256) {
        float v = xr[d];
        s += v * v;
    }
    __shared__ float red[8];
    #pragma unroll
    for (int o = 16; o; o >>= 1) s += __shfl_xor_sync(0xffffffffu, s, o);
    if ((threadIdx.x & 31) == 0) red[threadIdx.x >> 5] = s;
    __syncthreads();
    if (threadIdx.x < 8) {
        float t = red[threadIdx.x];
        #pragma unroll
        for (int o = 4; o; o >>= 1) t += __shfl_xor_sync(0xffu, t, o);
        if (threadIdx.x == 0) red[0] = rsqrtf(t / (float)DM + 1e-5f);
    }
    __syncthreads();
    float rinv = red[0];
    for (int d = threadIdx.x; d < DM; d += 256)
        g_xn[(size_t)l * DM + d] = xr[d] * rinv * w[d];
}

__global__ void conv_silu_kernel(const float* __restrict__ w,
                                 const float* __restrict__ b) {
    int i = blockIdx.x * blockDim.x + threadIdx.x;
    if (i >= LSEQ * DI) return;
    int l = i / DI, d = i - l * DI;
    float s = b[d];
    #pragma unroll
    for (int k = 0; k < DCONV; k++) {
        int ll = l - (DCONV - 1) + k;
        if (ll >= 0) s = fmaf(w[d * DCONV + k], g_xz[(size_t)ll * DXZ + d], s);
    }
    float sig = 1.f / (1.f + __expf(-s));
    g_xr[i] = s * sig;
}

// ---------------- generic tiled fp32 GEMM (64x64x16, 4x4/thread) ----------------
// MODE 0: C = A@B   MODE 1: C = softplus(A@B + bias)   MODE 2: C = addsrc + A@B
template<int MODE>
__device__ __forceinline__ void gemm_body(
        const float* __restrict__ A, int lda,
        const float* __restrict__ B,
        float* __restrict__ C,
        int M, int N, int K,
        const float* __restrict__ bias,
        const float* __restrict__ addsrc)
{
    __shared__ float sA[16][65];   // +1 pad: conflict-free stores
    __shared__ float sB[16][64];   // aligned float4 reads

    int tid = threadIdx.x;               // 0..255
    int tx = tid & 15, ty = tid >> 4;
    int row0 = blockIdx.y * 64;
    int col0 = blockIdx.x * 64;

    float acc[4][4] = {};

    for (int k0 = 0; k0 < K; k0 += 16) {
        {   // load A tile 64x16 as one float4 per thread
            int m  = tid >> 2;
            int k4 = (tid & 3) * 4;
            const float4 v = *reinterpret_cast<const float4*>(
                &A[(size_t)(row0 + m) * lda + k0 + k4]);
            sA[k4 + 0][m] = v.x; sA[k4 + 1][m] = v.y;
            sA[k4 + 2][m] = v.z; sA[k4 + 3][m] = v.w;
        }
        #pragma unroll
        for (int i = 0; i < 4; i++) {    // load B tile 16x64
            int idx = tid + i * 256;
            int k = idx >> 6, n = idx & 63;
            float v = 0.f;
            if (col0 + n < N) v = B[(size_t)(k0 + k) * N + col0 + n];
            sB[k][n] = v;
        }
        __syncthreads();
        #pragma unroll
        for (int kk = 0; kk < 16; kk++) {
            float ra[4], rb[4];
            #pragma unroll
            for (int i = 0; i < 4; i++) ra[i] = sA[kk][ty * 4 + i];
            #pragma unroll
            for (int j = 0; j < 4; j++) rb[j] = sB[kk][tx * 4 + j];
            #pragma unroll
            for (int i = 0; i < 4; i++)
                #pragma unroll
                for (int j = 0; j < 4; j++)
                    acc[i][j] = fmaf(ra[i], rb[j], acc[i][j]);
        }
        __syncthreads();
    }

    #pragma unroll
    for (int i = 0; i < 4; i++) {
        int m = row0 + ty * 4 + i;
        #pragma unroll
        for (int j = 0; j < 4; j++) {
            int n = col0 + tx * 4 + j;
            if (n >= N) continue;
            float v = acc[i][j];
            if (MODE == 1) {
                v += bias[n];
                v = (v > 20.f) ? v : log1pf(__expf(v));
            } else if (MODE == 2) {
                v += addsrc[(size_t)m * N + n];
            }
            C[(size_t)m * N + n] = v;
        }
    }
}

__global__ void gemm_in_proj_kernel(const float* __restrict__ W) {
    gemm_body<0>(g_xn, DM, W, g_xz, LSEQ, DXZ, DM, nullptr, nullptr);
}
__global__ void gemm_x_proj_kernel(const float* __restrict__ W) {
    gemm_body<0>(g_xr, DI, W, g_xdbl, LSEQ, XDBL, DI, nullptr, nullptr);
}
__global__ void gemm_dt_proj_kernel(const float* __restrict__ W,
                                    const float* __restrict__ b) {
    gemm_body<1>(g_xdbl, XDBL, W, g_delta, LSEQ, DI, DTR, b, nullptr);
}
__global__ void gemm_out_proj_kernel(const float* __restrict__ W,
                                     float* __restrict__ dout, int use_dout) {
    float* dest = use_dout ? dout : g_x;
    gemm_body<2>(g_ya, DI, W, dest, LSEQ, DM, DI, nullptr, g_x);
}

// ---------------- chunked selective scan ----------------
// Phase A: per (d, chunk) compute chunk-local (A-product, end state), h starting at 0.
__global__ void scan_phaseA_kernel(const float* __restrict__ A_log) {
    int d = blockIdx.x * blockDim.x + threadIdx.x;   // 0..DI-1
    int chunk = blockIdx.y;
    float Arow[DS], h[DS], P[DS];
    #pragma unroll
    for (int n = 0; n < DS; n++) {
        Arow[n] = -__expf(A_log[(size_t)d * DS + n]);
        h[n] = 0.f; P[n] = 1.f;
    }
    int l0 = chunk * CLEN;
    for (int l = l0; l < l0 + CLEN; l++) {
        float dl = g_delta[(size_t)l * DI + d];
        float du = dl * g_xr[(size_t)l * DI + d];
        const float* Bp = &g_xdbl[(size_t)l * XDBL + DTR];
        #pragma unroll
        for (int n = 0; n < DS; n++) {
            float a = __expf(dl * Arow[n]);
            h[n] = fmaf(a, h[n], du * Bp[n]);
            P[n] *= a;
        }
    }
    size_t base = ((size_t)chunk * DI + d) * DS;
    #pragma unroll
    for (int n = 0; n < DS; n++) {
        g_Aprod[base + n] = P[n];
        g_Hend [base + n] = h[n];
    }
}

// Phase B: 16-step inter-chunk scan per (d, n).
__global__ void scan_phaseB_kernel() {
    int i = blockIdx.x * blockDim.x + threadIdx.x;   // 0..DI*DS-1
    if (i >= DI * DS) return;
    float run = 0.f;
    #pragma unroll
    for (int c = 0; c < NCH; c++) {
        size_t idx = (size_t)c * DI * DS + i;
        g_Hinit[idx] = run;
        run = fmaf(g_Aprod[idx], run, g_Hend[idx]);
    }
}

// Phase C: recompute with correct initial state, emit ya = (y + u*D) * silu(res).
__global__ void scan_phaseC_kernel(const float* __restrict__ A_log,
                                   const float* __restrict__ Dp) {
    int d = blockIdx.x * blockDim.x + threadIdx.x;
    int chunk = blockIdx.y;
    float Arow[DS], h[DS];
    size_t base = ((size_t)chunk * DI + d) * DS;
    #pragma unroll
    for (int n = 0; n < DS; n++) {
        Arow[n] = -__expf(A_log[(size_t)d * DS + n]);
        h[n] = g_Hinit[base + n];
    }
    float Dd = Dp[d];
    int l0 = chunk * CLEN;
    for (int l = l0; l < l0 + CLEN; l++) {
        float dl = g_delta[(size_t)l * DI + d];
        float u  = g_xr[(size_t)l * DI + d];
        float du = dl * u;
        const float* Bp = &g_xdbl[(size_t)l * XDBL + DTR];
        const float* Cp = &g_xdbl[(size_t)l * XDBL + DTR + DS];
        float y = 0.f;
        #pragma unroll
        for (int n = 0; n < DS; n++) {
            float a = __expf(dl * Arow[n]);
            h[n] = fmaf(a, h[n], du * Bp[n]);
            y = fmaf(h[n], Cp[n], y);
        }
        y = fmaf(u, Dd, y);
        float res = g_xz[(size_t)l * DXZ + DI + d];
        float sig = 1.f / (1.f + __expf(-res));
        g_ya[(size_t)l * DI + d] = y * (res * sig);
    }
}

// ---------------- launcher ----------------
extern "C" void kernel_launch(void* const* d_in, const int* in_sizes, int n_in,
                              void* d_out, int out_size) {
    const int*   ids        = (const int*)  d_in[0];
    const float* emb        = (const float*)d_in[1];
    const float* norm_w     = (const float*)d_in[2];
    const float* in_proj_w  = (const float*)d_in[3];
    const float* conv_w     = (const float*)d_in[4];
    const float* conv_b     = (const float*)d_in[5];
    const float* x_proj_w   = (const float*)d_in[6];
    const float* dt_proj_w  = (const float*)d_in[7];
    const float* dt_proj_b  = (const float*)d_in[8];
    const float* A_log      = (const float*)d_in[9];
    const float* Dp         = (const float*)d_in[10];
    const float* out_proj_w = (const float*)d_in[11];
    float* out = (float*)d_out;

    embed_kernel<<<(LSEQ * DM + 255) / 256, 256>>>(ids, emb);

    for (int layer = 0; layer < NLAYER; layer++) {
        rmsnorm_kernel<<<LSEQ, 256>>>(norm_w + (size_t)layer * DM);

        gemm_in_proj_kernel<<<dim3(DXZ / 64, LSEQ / 64), 256>>>(
            in_proj_w + (size_t)layer * DM * DXZ);

        conv_silu_kernel<<<(LSEQ * DI + 255) / 256, 256>>>(
            conv_w + (size_t)layer * DI * DCONV,
            conv_b + (size_t)layer * DI);

        gemm_x_proj_kernel<<<dim3((XDBL + 63) / 64, LSEQ / 64), 256>>>(
            x_proj_w + (size_t)layer * DI * XDBL);

        gemm_dt_proj_kernel<<<dim3(DI / 64, LSEQ / 64), 256>>>(
            dt_proj_w + (size_t)layer * DTR * DI,
            dt_proj_b + (size_t)layer * DI);

        scan_phaseA_kernel<<<dim3(DI / 128, NCH), 128>>>(
            A_log + (size_t)layer * DI * DS);

        scan_phaseB_kernel<<<(DI * DS + 255) / 256, 256>>>();

        scan_phaseC_kernel<<<dim3(DI / 128, NCH), 128>>>(
            A_log + (size_t)layer * DI * DS,
            Dp + (size_t)layer * DI);

        gemm_out_proj_kernel<<<dim3(DM / 64, LSEQ / 64), 256>>>(
            out_proj_w + (size_t)layer * DI * DM,
            out, layer == NLAYER - 1);
    }
}

// round 3
// speedup vs baseline: 1.7689x; 1.7689x over previous
#include <cuda_runtime.h>
#include <cuda_bf16.h>
#include <math.h>
#include <stdint.h>

// ---------------- problem constants ----------------
#define LSEQ   2048
#define DM     768
#define DI     1536          // 2*DM
#define DXZ    3072          // 2*DI
#define DTR    48
#define DS     16
#define DCONV  4
#define NLAYER 2
#define XDBL   80            // DTR + 2*DS
#define NCH    16
#define CLEN   128           // LSEQ / NCH

// ---------------- scratch (device globals, no allocation) ----------------
__device__ __align__(16) float g_x   [LSEQ * DM];    // residual stream
__device__ __align__(16) float g_xz  [LSEQ * DXZ];   // in_proj output (xr | res)
__device__ __align__(16) float g_xr  [LSEQ * DI];    // conv+silu output
__device__ __align__(16) float g_xdbl[LSEQ * XDBL];  // x_proj output (dt | B | C)
__device__ __align__(16) float g_delta[LSEQ * DI];   // softplus(dt@dt_proj + b)
__device__ __align__(16) float g_Aprod[NCH * DI * DS];
__device__ __align__(16) float g_Hend [NCH * DI * DS];
__device__ __align__(16) float g_Hinit[NCH * DI * DS];

// bf16 hi/lo split operands for tensor-core GEMMs
__device__ __align__(16) __nv_bfloat16 g_xn_hi[LSEQ * DM];
__device__ __align__(16) __nv_bfloat16 g_xn_lo[LSEQ * DM];
__device__ __align__(16) __nv_bfloat16 g_ya_hi[LSEQ * DI];
__device__ __align__(16) __nv_bfloat16 g_ya_lo[LSEQ * DI];
#define WMAX (DM * DXZ)     // >= DI*DM too
__device__ __align__(16) __nv_bfloat16 g_wt_hi[WMAX]; // transposed weight [N][K]
__device__ __align__(16) __nv_bfloat16 g_wt_lo[WMAX];

// ---------------- small helpers ----------------
__device__ __forceinline__ uint32_t smem_u32(const void* p) {
    uint32_t a;
    asm("{ .reg .u64 t; cvta.to.shared.u64 t, %1; cvt.u32.u64 %0, t; }"
        : "=r"(a) : "l"(p));
    return a;
}
__device__ __forceinline__ void ldm4(uint32_t addr, uint32_t r[4]) {
    asm volatile("ldmatrix.sync.aligned.m8n8.x4.shared.b16 {%0,%1,%2,%3}, [%4];"
                 : "=r"(r[0]), "=r"(r[1]), "=r"(r[2]), "=r"(r[3]) : "r"(addr));
}
__device__ __forceinline__ void mma16816(float c[4], const uint32_t a[4],
                                         const uint32_t b0, const uint32_t b1) {
    asm volatile(
        "mma.sync.aligned.m16n8k16.row.col.f32.bf16.bf16.f32 "
        "{%0,%1,%2,%3}, {%4,%5,%6,%7}, {%8,%9}, {%0,%1,%2,%3};"
        : "+f"(c[0]), "+f"(c[1]), "+f"(c[2]), "+f"(c[3])
        : "r"(a[0]), "r"(a[1]), "r"(a[2]), "r"(a[3]), "r"(b0), "r"(b1));
}

// ---------------- bf16-split GEMM via mma.sync ----------------
// C[M,N] = (Ah+Al)[M,K] @ (Bh+Bl)^T  with B supplied as [N][K] row-major.
// 3-term split: AhBh + AhBl + AlBh.  Tile 128x128, K-slab 32, 2-stage cp.async.
#define SROW   40                       // 32 bf16 + 8 pad (80B rows)
#define TILE_E (128 * SROW)             // elems per tile
#define SMEM_MMA (2 * 4 * TILE_E * 2)   // 2 stages x 4 tiles x bf16 = 81920 B

__device__ __forceinline__ void mma_load_stage(
        uint32_t smb, int stage,
        const __nv_bfloat16* __restrict__ Ah, const __nv_bfloat16* __restrict__ Al,
        const __nv_bfloat16* __restrict__ Bh, const __nv_bfloat16* __restrict__ Bl,
        int row0, int col0, int k0, int K, int tid) {
    #pragma unroll
    for (int t = 0; t < 4; t++) {
        const __nv_bfloat16* src = (t == 0) ? Ah : (t == 1) ? Al : (t == 2) ? Bh : Bl;
        int r0 = (t < 2) ? row0 : col0;
        #pragma unroll
        for (int i = 0; i < 2; i++) {
            int c = tid + i * 256;
            int row = c >> 2, kc = (c & 3) * 8;
            uint32_t dst = smb + (uint32_t)(((stage * 4 + t) * TILE_E) + row * SROW + kc) * 2u;
            const void* gsrc = src + (size_t)(r0 + row) * K + k0 + kc;
            asm volatile("cp.async.cg.shared.global [%0], [%1], 16;"
                         :: "r"(dst), "l"(gsrc));
        }
    }
    asm volatile("cp.async.commit_group;" ::: "memory");
}

// MODE 0: C = A@B    MODE 2: C = addsrc + A@B
template<int MODE>
__global__ void __launch_bounds__(256)
gemm_mma_kernel(const __nv_bfloat16* __restrict__ Ahg, const __nv_bfloat16* __restrict__ Alg,
                const __nv_bfloat16* __restrict__ Bhg, const __nv_bfloat16* __restrict__ Blg,
                float* __restrict__ C, const float* __restrict__ addsrc, int K, int N) {
    extern __shared__ __nv_bfloat16 sm[];
    const int tid = threadIdx.x, lane = tid & 31, wid = tid >> 5;
    const int wm = wid & 3, wn = wid >> 2;         // 4 m-warps x 2 n-warps
    const int row0 = blockIdx.y * 128, col0 = blockIdx.x * 128;
    uint32_t smb = smem_u32(sm);

    float acc[2][8][4] = {};
    const int S = K / 32;

    mma_load_stage(smb, 0, Ahg, Alg, Bhg, Blg, row0, col0, 0, K, tid);

    const int lrow = lane & 15, lcol = (lane >> 4) * 8;

    for (int s = 0; s < S; s++) {
        if (s + 1 < S) {
            mma_load_stage(smb, (s + 1) & 1, Ahg, Alg, Bhg, Blg,
                           row0, col0, (s + 1) * 32, K, tid);
            asm volatile("cp.async.wait_group 1;" ::: "memory");
        } else {
            asm volatile("cp.async.wait_group 0;" ::: "memory");
        }
        __syncthreads();

        int st = s & 1;
        uint32_t bAh = smb + (uint32_t)((st * 4 + 0) * TILE_E) * 2u;
        uint32_t bAl = smb + (uint32_t)((st * 4 + 1) * TILE_E) * 2u;
        uint32_t bBh = smb + (uint32_t)((st * 4 + 2) * TILE_E) * 2u;
        uint32_t bBl = smb + (uint32_t)((st * 4 + 3) * TILE_E) * 2u;

        #pragma unroll
        for (int kk = 0; kk < 32; kk += 16) {
            uint32_t ah[2][4], al[2][4];
            #pragma unroll
            for (int mt = 0; mt < 2; mt++) {
                uint32_t off = (uint32_t)((wm * 32 + mt * 16 + lrow) * SROW + kk + lcol) * 2u;
                ldm4(bAh + off, ah[mt]);
                ldm4(bAl + off, al[mt]);
            }
            #pragma unroll
            for (int g = 0; g < 4; g++) {
                uint32_t b4h[4], b4l[4];
                uint32_t off = (uint32_t)((wn * 64 + g * 16 + lrow) * SROW + kk + lcol) * 2u;
                ldm4(bBh + off, b4h);
                ldm4(bBl + off, b4l);
                #pragma unroll
                for (int mt = 0; mt < 2; mt++) {
                    mma16816(acc[mt][2 * g + 0], ah[mt], b4h[0], b4h[2]);
                    mma16816(acc[mt][2 * g + 0], ah[mt], b4l[0], b4l[2]);
                    mma16816(acc[mt][2 * g + 0], al[mt], b4h[0], b4h[2]);
                    mma16816(acc[mt][2 * g + 1], ah[mt], b4h[1], b4h[3]);
                    mma16816(acc[mt][2 * g + 1], ah[mt], b4l[1], b4l[3]);
                    mma16816(acc[mt][2 * g + 1], al[mt], b4h[1], b4h[3]);
                }
            }
        }
        __syncthreads();
    }

    // epilogue
    int gq = lane >> 2, tq = lane & 3;
    #pragma unroll
    for (int mt = 0; mt < 2; mt++) {
        #pragma unroll
        for (int n8 = 0; n8 < 8; n8++) {
            int rm = row0 + wm * 32 + mt * 16 + gq;
            int cn = col0 + wn * 64 + n8 * 8 + 2 * tq;
            size_t i0 = (size_t)rm * N + cn;
            size_t i1 = (size_t)(rm + 8) * N + cn;
            float2 v0 = make_float2(acc[mt][n8][0], acc[mt][n8][1]);
            float2 v1 = make_float2(acc[mt][n8][2], acc[mt][n8][3]);
            if (MODE == 2) {
                float2 a0 = *reinterpret_cast<const float2*>(addsrc + i0);
                float2 a1 = *reinterpret_cast<const float2*>(addsrc + i1);
                v0.x += a0.x; v0.y += a0.y;
                v1.x += a1.x; v1.y += a1.y;
            }
            *reinterpret_cast<float2*>(C + i0) = v0;
            *reinterpret_cast<float2*>(C + i1) = v1;
        }
    }
}

// ---------------- elementwise kernels ----------------
__global__ void embed_kernel(const int* __restrict__ ids,
                             const float* __restrict__ emb) {
    int i = blockIdx.x * blockDim.x + threadIdx.x;
    if (i >= LSEQ * DM) return;
    int l = i / DM, d = i - l * DM;
    g_x[i] = emb[(size_t)ids[l] * DM + d];
}

// rmsnorm fused with bf16 hi/lo split output
__global__ void rmsnorm_kernel(const float* __restrict__ w) {
    int l = blockIdx.x;
    const float* xr = &g_x[(size_t)l * DM];
    float s = 0.f;
    for (int d = threadIdx.x; d < DM; d += 256) {
        float v = xr[d];
        s += v * v;
    }
    __shared__ float red[8];
    #pragma unroll
    for (int o = 16; o; o >>= 1) s += __shfl_xor_sync(0xffffffffu, s, o);
    if ((threadIdx.x & 31) == 0) red[threadIdx.x >> 5] = s;
    __syncthreads();
    if (threadIdx.x < 8) {
        float t = red[threadIdx.x];
        #pragma unroll
        for (int o = 4; o; o >>= 1) t += __shfl_xor_sync(0xffu, t, o);
        if (threadIdx.x == 0) red[0] = rsqrtf(t / (float)DM + 1e-5f);
    }
    __syncthreads();
    float rinv = red[0];
    for (int d = threadIdx.x; d < DM; d += 256) {
        float v = xr[d] * rinv * w[d];
        __nv_bfloat16 hi = __float2bfloat16(v);
        __nv_bfloat16 lo = __float2bfloat16(v - __bfloat162float(hi));
        g_xn_hi[(size_t)l * DM + d] = hi;
        g_xn_lo[(size_t)l * DM + d] = lo;
    }
}

// transpose+split weights: W fp32 [K][N] -> hi/lo bf16 [N][K]
__global__ void wconv_kernel(const float* __restrict__ W,
                             __nv_bfloat16* __restrict__ hi,
                             __nv_bfloat16* __restrict__ lo, int K, int N) {
    __shared__ float t[32][33];
    int k0 = blockIdx.x * 32, n0 = blockIdx.y * 32;
    #pragma unroll
    for (int i = 0; i < 4; i++)
        t[threadIdx.y + i * 8][threadIdx.x] =
            W[(size_t)(k0 + threadIdx.y + i * 8) * N + n0 + threadIdx.x];
    __syncthreads();
    #pragma unroll
    for (int i = 0; i < 4; i++) {
        float v = t[threadIdx.x][threadIdx.y + i * 8];
        __nv_bfloat16 h = __float2bfloat16(v);
        __nv_bfloat16 l = __float2bfloat16(v - __bfloat162float(h));
        size_t idx = (size_t)(n0 + threadIdx.y + i * 8) * K + k0 + threadIdx.x;
        hi[idx] = h;
        lo[idx] = l;
    }
}

__global__ void conv_silu_kernel(const float* __restrict__ w,
                                 const float* __restrict__ b) {
    int i = blockIdx.x * blockDim.x + threadIdx.x;
    if (i >= LSEQ * DI) return;
    int l = i / DI, d = i - l * DI;
    float s = b[d];
    #pragma unroll
    for (int k = 0; k < DCONV; k++) {
        int ll = l - (DCONV - 1) + k;
        if (ll >= 0) s = fmaf(w[d * DCONV + k], g_xz[(size_t)ll * DXZ + d], s);
    }
    float sig = 1.f / (1.f + __expf(-s));
    g_xr[i] = s * sig;
}

// ---------------- SIMT fp32 GEMM (small shapes: x_proj, dt_proj) ----------------
// MODE 0: C = A@B   MODE 1: C = softplus(A@B + bias)
template<int MODE>
__device__ __forceinline__ void gemm_body(
        const float* __restrict__ A, int lda,
        const float* __restrict__ B,
        float* __restrict__ C,
        int M, int N, int K,
        const float* __restrict__ bias) {
    __shared__ float sA[16][65];
    __shared__ float sB[16][64];
    int tid = threadIdx.x;
    int tx = tid & 15, ty = tid >> 4;
    int row0 = blockIdx.y * 64;
    int col0 = blockIdx.x * 64;
    float acc[4][4] = {};
    for (int k0 = 0; k0 < K; k0 += 16) {
        {
            int m  = tid >> 2;
            int k4 = (tid & 3) * 4;
            const float4 v = *reinterpret_cast<const float4*>(
                &A[(size_t)(row0 + m) * lda + k0 + k4]);
            sA[k4 + 0][m] = v.x; sA[k4 + 1][m] = v.y;
            sA[k4 + 2][m] = v.z; sA[k4 + 3][m] = v.w;
        }
        #pragma unroll
        for (int i = 0; i < 4; i++) {
            int idx = tid + i * 256;
            int k = idx >> 6, n = idx & 63;
            float v = 0.f;
            if (col0 + n < N) v = B[(size_t)(k0 + k) * N + col0 + n];
            sB[k][n] = v;
        }
        __syncthreads();
        #pragma unroll
        for (int kk = 0; kk < 16; kk++) {
            float ra[4], rb[4];
            #pragma unroll
            for (int i = 0; i < 4; i++) ra[i] = sA[kk][ty * 4 + i];
            #pragma unroll
            for (int j = 0; j < 4; j++) rb[j] = sB[kk][tx * 4 + j];
            #pragma unroll
            for (int i = 0; i < 4; i++)
                #pragma unroll
                for (int j = 0; j < 4; j++)
                    acc[i][j] = fmaf(ra[i], rb[j], acc[i][j]);
        }
        __syncthreads();
    }
    #pragma unroll
    for (int i = 0; i < 4; i++) {
        int m = row0 + ty * 4 + i;
        #pragma unroll
        for (int j = 0; j < 4; j++) {
            int n = col0 + tx * 4 + j;
            if (n >= N) continue;
            float v = acc[i][j];
            if (MODE == 1) {
                v += bias[n];
                v = (v > 20.f) ? v : log1pf(__expf(v));
            }
            C[(size_t)m * N + n] = v;
        }
    }
}

__global__ void gemm_x_proj_kernel(const float* __restrict__ W) {
    gemm_body<0>(g_xr, DI, W, g_xdbl, LSEQ, XDBL, DI, nullptr);
}
__global__ void gemm_dt_proj_kernel(const float* __restrict__ W,
                                    const float* __restrict__ b) {
    gemm_body<1>(g_xdbl, XDBL, W, g_delta, LSEQ, DI, DTR, b);
}

// ---------------- chunked selective scan (power-chain exp) ----------------
__global__ void scan_phaseA_kernel(const float* __restrict__ A_log) {
    int d = blockIdx.x * blockDim.x + threadIdx.x;
    int chunk = blockIdx.y;
    __shared__ float sB[CLEN][DS];
    int l0 = chunk * CLEN;
    for (int idx = threadIdx.x; idx < CLEN * DS; idx += blockDim.x) {
        int l = idx >> 4, n = idx & 15;
        sB[l][n] = g_xdbl[(size_t)(l0 + l) * XDBL + DTR + n];
    }
    __syncthreads();

    float Arow[DS], h[DS], P[DS];
    bool chain = true;
    #pragma unroll
    for (int n = 0; n < DS; n++) {
        Arow[n] = -__expf(A_log[(size_t)d * DS + n]);
        h[n] = 0.f; P[n] = 1.f;
    }
    float r0 = Arow[0];
    #pragma unroll
    for (int n = 1; n < DS; n++)
        chain = chain && (fabsf(Arow[n] - (float)(n + 1) * r0)
                          <= 1e-5f * fabsf(Arow[n]) + 1e-7f);

    if (chain) {
        for (int l = 0; l < CLEN; l++) {
            float dl = g_delta[(size_t)(l0 + l) * DI + d];
            float du = dl * g_xr[(size_t)(l0 + l) * DI + d];
            float q = __expf(dl * r0);
            float a = 1.f;
            #pragma unroll
            for (int n = 0; n < DS; n++) {
                a *= q;
                h[n] = fmaf(a, h[n], du * sB[l][n]);
                P[n] *= a;
            }
        }
    } else {
        for (int l = 0; l < CLEN; l++) {
            float dl = g_delta[(size_t)(l0 + l) * DI + d];
            float du = dl * g_xr[(size_t)(l0 + l) * DI + d];
            #pragma unroll
            for (int n = 0; n < DS; n++) {
                float a = __expf(dl * Arow[n]);
                h[n] = fmaf(a, h[n], du * sB[l][n]);
                P[n] *= a;
            }
        }
    }
    size_t base = ((size_t)chunk * DI + d) * DS;
    #pragma unroll
    for (int n = 0; n < DS; n++) {
        g_Aprod[base + n] = P[n];
        g_Hend [base + n] = h[n];
    }
}

__global__ void scan_phaseB_kernel() {
    int i = blockIdx.x * blockDim.x + threadIdx.x;
    if (i >= DI * DS) return;
    float run = 0.f;
    #pragma unroll
    for (int c = 0; c < NCH; c++) {
        size_t idx = (size_t)c * DI * DS + i;
        g_Hinit[idx] = run;
        run = fmaf(g_Aprod[idx], run, g_Hend[idx]);
    }
}

__global__ void scan_phaseC_kernel(const float* __restrict__ A_log,
                                   const float* __restrict__ Dp) {
    int d = blockIdx.x * blockDim.x + threadIdx.x;
    int chunk = blockIdx.y;
    __shared__ float sB[CLEN][DS];
    __shared__ float sC[CLEN][DS];
    int l0 = chunk * CLEN;
    for (int idx = threadIdx.x; idx < CLEN * DS; idx += blockDim.x) {
        int l = idx >> 4, n = idx & 15;
        sB[l][n] = g_xdbl[(size_t)(l0 + l) * XDBL + DTR + n];
        sC[l][n] = g_xdbl[(size_t)(l0 + l) * XDBL + DTR + DS + n];
    }
    __syncthreads();

    float Arow[DS], h[DS];
    bool chain = true;
    size_t base = ((size_t)chunk * DI + d) * DS;
    #pragma unroll
    for (int n = 0; n < DS; n++) {
        Arow[n] = -__expf(A_log[(size_t)d * DS + n]);
        h[n] = g_Hinit[base + n];
    }
    float r0 = Arow[0];
    #pragma unroll
    for (int n = 1; n < DS; n++)
        chain = chain && (fabsf(Arow[n] - (float)(n + 1) * r0)
                          <= 1e-5f * fabsf(Arow[n]) + 1e-7f);
    float Dd = Dp[d];

    for (int l = 0; l < CLEN; l++) {
        float dl = g_delta[(size_t)(l0 + l) * DI + d];
        float u  = g_xr[(size_t)(l0 + l) * DI + d];
        float du = dl * u;
        float y = 0.f;
        if (chain) {
            float q = __expf(dl * r0);
            float a = 1.f;
            #pragma unroll
            for (int n = 0; n < DS; n++) {
                a *= q;
                h[n] = fmaf(a, h[n], du * sB[l][n]);
                y = fmaf(h[n], sC[l][n], y);
            }
        } else {
            #pragma unroll
            for (int n = 0; n < DS; n++) {
                float a = __expf(dl * Arow[n]);
                h[n] = fmaf(a, h[n], du * sB[l][n]);
                y = fmaf(h[n], sC[l][n], y);
            }
        }
        y = fmaf(u, Dd, y);
        float res = g_xz[(size_t)(l0 + l) * DXZ + DI + d];
        float sig = 1.f / (1.f + __expf(-res));
        float ya = y * (res * sig);
        __nv_bfloat16 hi = __float2bfloat16(ya);
        __nv_bfloat16 lo = __float2bfloat16(ya - __bfloat162float(hi));
        g_ya_hi[(size_t)(l0 + l) * DI + d] = hi;
        g_ya_lo[(size_t)(l0 + l) * DI + d] = lo;
    }
}

// ---------------- launcher ----------------
extern "C" void kernel_launch(void* const* d_in, const int* in_sizes, int n_in,
                              void* d_out, int out_size) {
    const int*   ids        = (const int*)  d_in[0];
    const float* emb        = (const float*)d_in[1];
    const float* norm_w     = (const float*)d_in[2];
    const float* in_proj_w  = (const float*)d_in[3];
    const float* conv_w     = (const float*)d_in[4];
    const float* conv_b     = (const float*)d_in[5];
    const float* x_proj_w   = (const float*)d_in[6];
    const float* dt_proj_w  = (const float*)d_in[7];
    const float* dt_proj_b  = (const float*)d_in[8];
    const float* A_log      = (const float*)d_in[9];
    const float* Dp         = (const float*)d_in[10];
    const float* out_proj_w = (const float*)d_in[11];
    float* out = (float*)d_out;

    cudaFuncSetAttribute(gemm_mma_kernel<0>,
                         cudaFuncAttributeMaxDynamicSharedMemorySize, SMEM_MMA);
    cudaFuncSetAttribute(gemm_mma_kernel<2>,
                         cudaFuncAttributeMaxDynamicSharedMemorySize, SMEM_MMA);

    // resolve device-global scratch pointers
    __nv_bfloat16 *xn_hi, *xn_lo, *ya_hi, *ya_lo, *wt_hi, *wt_lo;
    float *xz, *x_res;
    cudaGetSymbolAddress((void**)&xn_hi, g_xn_hi);
    cudaGetSymbolAddress((void**)&xn_lo, g_xn_lo);
    cudaGetSymbolAddress((void**)&ya_hi, g_ya_hi);
    cudaGetSymbolAddress((void**)&ya_lo, g_ya_lo);
    cudaGetSymbolAddress((void**)&wt_hi, g_wt_hi);
    cudaGetSymbolAddress((void**)&wt_lo, g_wt_lo);
    cudaGetSymbolAddress((void**)&xz,    g_xz);
    cudaGetSymbolAddress((void**)&x_res, g_x);

    embed_kernel<<<(LSEQ * DM + 255) / 256, 256>>>(ids, emb);

    for (int layer = 0; layer < NLAYER; layer++) {
        rmsnorm_kernel<<<LSEQ, 256>>>(norm_w + (size_t)layer * DM);

        wconv_kernel<<<dim3(DM / 32, DXZ / 32), dim3(32, 8)>>>(
            in_proj_w + (size_t)layer * DM * DXZ, wt_hi, wt_lo, DM, DXZ);

        gemm_mma_kernel<0><<<dim3(DXZ / 128, LSEQ / 128), 256, SMEM_MMA>>>(
            xn_hi, xn_lo, wt_hi, wt_lo, xz, nullptr, DM, DXZ);

        conv_silu_kernel<<<(LSEQ * DI + 255) / 256, 256>>>(
            conv_w + (size_t)layer * DI * DCONV,
            conv_b + (size_t)layer * DI);

        gemm_x_proj_kernel<<<dim3((XDBL + 63) / 64, LSEQ / 64), 256>>>(
            x_proj_w + (size_t)layer * DI * XDBL);

        gemm_dt_proj_kernel<<<dim3(DI / 64, LSEQ / 64), 256>>>(
            dt_proj_w + (size_t)layer * DTR * DI,
            dt_proj_b + (size_t)layer * DI);

        scan_phaseA_kernel<<<dim3(DI / 128, NCH), 128>>>(
            A_log + (size_t)layer * DI * DS);

        scan_phaseB_kernel<<<(DI * DS + 255) / 256, 256>>>();

        scan_phaseC_kernel<<<dim3(DI / 128, NCH), 128>>>(
            A_log + (size_t)layer * DI * DS,
            Dp + (size_t)layer * DI);

        wconv_kernel<<<dim3(DI / 32, DM / 32), dim3(32, 8)>>>(
            out_proj_w + (size_t)layer * DI * DM, wt_hi, wt_lo, DI, DM);

        float* dest = (layer == NLAYER - 1) ? out : x_res;
        gemm_mma_kernel<2><<<dim3(DM / 128, LSEQ / 128), 256, SMEM_MMA>>>(
            ya_hi, ya_lo, wt_hi, wt_lo, dest, x_res, DI, DM);
    }
}

// round 4
// speedup vs baseline: 2.2661x; 1.2811x over previous
#include <cuda_runtime.h>
#include <cuda_bf16.h>
#include <math.h>
#include <stdint.h>

// ---------------- problem constants ----------------
#define LSEQ   2048
#define DM     768
#define DI     1536          // 2*DM
#define DXZ    3072          // 2*DI
#define DTR    48
#define DS     16
#define DCONV  4
#define NLAYER 2
#define XDBL   80            // DTR + 2*DS
#define NCH    16
#define CLEN   128           // LSEQ / NCH

// ---------------- scratch (device globals, no allocation) ----------------
__device__ __align__(16) float g_x   [LSEQ * DM];    // residual stream
__device__ __align__(16) float g_xz  [LSEQ * DXZ];   // in_proj output (xr | res)
__device__ __align__(16) float g_xr  [LSEQ * DI];    // conv+silu output (fp32 for scan)
__device__ __align__(16) float g_xdbl[LSEQ * XDBL];  // x_proj output (dt | B | C)
__device__ __align__(16) float g_delta[LSEQ * DI];   // softplus(dt@dt_proj + b)
__device__ __align__(16) float g_Aprod[NCH * DI * DS];
__device__ __align__(16) float g_Hend [NCH * DI * DS];
__device__ __align__(16) float g_Hinit[NCH * DI * DS];

// bf16 hi/lo split operands for tensor-core GEMMs
__device__ __align__(16) __nv_bfloat16 g_xn_hi[LSEQ * DM];
__device__ __align__(16) __nv_bfloat16 g_xn_lo[LSEQ * DM];
__device__ __align__(16) __nv_bfloat16 g_xr_hi[LSEQ * DI];
__device__ __align__(16) __nv_bfloat16 g_xr_lo[LSEQ * DI];
__device__ __align__(16) __nv_bfloat16 g_ya_hi[LSEQ * DI];
__device__ __align__(16) __nv_bfloat16 g_ya_lo[LSEQ * DI];
#define WMAX (DM * DXZ)     // >= DI*DM too
__device__ __align__(16) __nv_bfloat16 g_wt_hi[WMAX];       // transposed weight [N][K]
__device__ __align__(16) __nv_bfloat16 g_wt_lo[WMAX];
__device__ __align__(16) __nv_bfloat16 g_wxp_hi[128 * DI];  // x_proj weight [80->128 pad][1536]
__device__ __align__(16) __nv_bfloat16 g_wxp_lo[128 * DI];  // rows 80..127 stay zero forever
// split-K partials: max(3 * 2048*768, 8 * 2048*80)
__device__ __align__(16) float g_part[3 * LSEQ * DM];

// ---------------- small helpers ----------------
__device__ __forceinline__ uint32_t smem_u32(const void* p) {
    uint32_t a;
    asm("{ .reg .u64 t; cvta.to.shared.u64 t, %1; cvt.u32.u64 %0, t; }"
        : "=r"(a) : "l"(p));
    return a;
}
__device__ __forceinline__ void ldm4(uint32_t addr, uint32_t r[4]) {
    asm volatile("ldmatrix.sync.aligned.m8n8.x4.shared.b16 {%0,%1,%2,%3}, [%4];"
                 : "=r"(r[0]), "=r"(r[1]), "=r"(r[2]), "=r"(r[3]) : "r"(addr));
}
__device__ __forceinline__ void mma16816(float c[4], const uint32_t a[4],
                                         const uint32_t b0, const uint32_t b1) {
    asm volatile(
        "mma.sync.aligned.m16n8k16.row.col.f32.bf16.bf16.f32 "
        "{%0,%1,%2,%3}, {%4,%5,%6,%7}, {%8,%9}, {%0,%1,%2,%3};"
        : "+f"(c[0]), "+f"(c[1]), "+f"(c[2]), "+f"(c[3])
        : "r"(a[0]), "r"(a[1]), "r"(a[2]), "r"(a[3]), "r"(b0), "r"(b1));
}

// ---------------- bf16-split GEMM via mma.sync, 3-stage pipeline ----------------
// C[2048,N] = (Ah+Al)[2048,K] @ (Bh+Bl)^T with B as [N][K] row-major.
// 3-term split: AhBh + AhBl + AlBh.  Tile 128x128, K-slab 32, 3-stage cp.async.
// Split-K over blockIdx.z (ksize cols each); partial z writes C + z*2048*ldc.
#define SROW    40                       // 32 bf16 + 8 pad
#define TILE_E  (128 * SROW)
#define NSTAGE  3
#define SMEM_MMA (NSTAGE * 4 * TILE_E * 2)   // 122880 B

__device__ __forceinline__ void mma_load_stage(
        uint32_t smb, int stage,
        const __nv_bfloat16* __restrict__ Ah, const __nv_bfloat16* __restrict__ Al,
        const __nv_bfloat16* __restrict__ Bh, const __nv_bfloat16* __restrict__ Bl,
        int row0, int col0, int k0, int K, int tid) {
    #pragma unroll
    for (int t = 0; t < 4; t++) {
        const __nv_bfloat16* src = (t == 0) ? Ah : (t == 1) ? Al : (t == 2) ? Bh : Bl;
        int r0 = (t < 2) ? row0 : col0;
        #pragma unroll
        for (int i = 0; i < 2; i++) {
            int c = tid + i * 256;
            int row = c >> 2, kc = (c & 3) * 8;
            uint32_t dst = smb + (uint32_t)(((stage * 4 + t) * TILE_E) + row * SROW + kc) * 2u;
            const void* gsrc = src + (size_t)(r0 + row) * K + k0 + kc;
            asm volatile("cp.async.cg.shared.global [%0], [%1], 16;"
                         :: "r"(dst), "l"(gsrc));
        }
    }
}

__global__ void __launch_bounds__(256)
gemm_mma3_kernel(const __nv_bfloat16* __restrict__ Ahg, const __nv_bfloat16* __restrict__ Alg,
                 const __nv_bfloat16* __restrict__ Bhg, const __nv_bfloat16* __restrict__ Blg,
                 float* __restrict__ C, int K, int ksize, int ldc, int Nvalid) {
    extern __shared__ __nv_bfloat16 sm[];
    const int tid = threadIdx.x, lane = tid & 31, wid = tid >> 5;
    const int wm = wid & 3, wn = wid >> 2;         // 4 m-warps x 2 n-warps
    const int row0 = blockIdx.y * 128, col0 = blockIdx.x * 128;
    const int kb = blockIdx.z * ksize;
    C += (size_t)blockIdx.z * LSEQ * ldc;
    uint32_t smb = smem_u32(sm);

    float acc[2][8][4] = {};
    const int S = ksize / 32;

    mma_load_stage(smb, 0, Ahg, Alg, Bhg, Blg, row0, col0, kb, K, tid);
    asm volatile("cp.async.commit_group;" ::: "memory");
    mma_load_stage(smb, 1, Ahg, Alg, Bhg, Blg, row0, col0, kb + 32, K, tid);
    asm volatile("cp.async.commit_group;" ::: "memory");

    const int lrow = lane & 15, lcol = (lane >> 4) * 8;

    for (int s = 0; s < S; s++) {
        if (s + 2 < S)
            mma_load_stage(smb, (s + 2) % NSTAGE, Ahg, Alg, Bhg, Blg,
                           row0, col0, kb + (s + 2) * 32, K, tid);
        asm volatile("cp.async.commit_group;" ::: "memory");
        asm volatile("cp.async.wait_group 2;" ::: "memory");
        __syncthreads();

        int st = s % NSTAGE;
        uint32_t bAh = smb + (uint32_t)((st * 4 + 0) * TILE_E) * 2u;
        uint32_t bAl = smb + (uint32_t)((st * 4 + 1) * TILE_E) * 2u;
        uint32_t bBh = smb + (uint32_t)((st * 4 + 2) * TILE_E) * 2u;
        uint32_t bBl = smb + (uint32_t)((st * 4 + 3) * TILE_E) * 2u;

        #pragma unroll
        for (int kk = 0; kk < 32; kk += 16) {
            uint32_t ah[2][4], al[2][4];
            #pragma unroll
            for (int mt = 0; mt < 2; mt++) {
                uint32_t off = (uint32_t)((wm * 32 + mt * 16 + lrow) * SROW + kk + lcol) * 2u;
                ldm4(bAh + off, ah[mt]);
                ldm4(bAl + off, al[mt]);
            }
            #pragma unroll
            for (int g = 0; g < 4; g++) {
                uint32_t b4h[4], b4l[4];
                uint32_t off = (uint32_t)((wn * 64 + g * 16 + lrow) * SROW + kk + lcol) * 2u;
                ldm4(bBh + off, b4h);
                ldm4(bBl + off, b4l);
                #pragma unroll
                for (int mt = 0; mt < 2; mt++) {
                    mma16816(acc[mt][2 * g + 0], ah[mt], b4h[0], b4h[2]);
                    mma16816(acc[mt][2 * g + 0], ah[mt], b4l[0], b4l[2]);
                    mma16816(acc[mt][2 * g + 0], al[mt], b4h[0], b4h[2]);
                    mma16816(acc[mt][2 * g + 1], ah[mt], b4h[1], b4h[3]);
                    mma16816(acc[mt][2 * g + 1], ah[mt], b4l[1], b4l[3]);
                    mma16816(acc[mt][2 * g + 1], al[mt], b4h[1], b4h[3]);
                }
            }
        }
        __syncthreads();
    }

    // epilogue: raw partial/full write
    int gq = lane >> 2, tq = lane & 3;
    #pragma unroll
    for (int mt = 0; mt < 2; mt++) {
        #pragma unroll
        for (int n8 = 0; n8 < 8; n8++) {
            int rm = row0 + wm * 32 + mt * 16 + gq;
            int cn = col0 + wn * 64 + n8 * 8 + 2 * tq;
            if (cn >= Nvalid) continue;
            float2 v0 = make_float2(acc[mt][n8][0], acc[mt][n8][1]);
            float2 v1 = make_float2(acc[mt][n8][2], acc[mt][n8][3]);
            *reinterpret_cast<float2*>(C + (size_t)rm * ldc + cn) = v0;
            *reinterpret_cast<float2*>(C + (size_t)(rm + 8) * ldc + cn) = v1;
        }
    }
}

// reduce 8 x_proj split-K partials -> g_xdbl
__global__ void xproj_reduce_kernel() {
    int i = blockIdx.x * blockDim.x + threadIdx.x;
    if (i >= LSEQ * XDBL) return;
    float s = 0.f;
    #pragma unroll
    for (int z = 0; z < 8; z++) s += g_part[(size_t)z * LSEQ * XDBL + i];
    g_xdbl[i] = s;
}

// reduce 3 out_proj split-K partials + residual -> dest
__global__ void outproj_reduce_kernel(float* __restrict__ dest) {
    int i = blockIdx.x * blockDim.x + threadIdx.x;
    if (i >= LSEQ * DM) return;
    float s = g_x[i];
    #pragma unroll
    for (int z = 0; z < 3; z++) s += g_part[(size_t)z * LSEQ * DM + i];
    dest[i] = s;
}

// ---------------- elementwise kernels ----------------
__global__ void embed_kernel(const int* __restrict__ ids,
                             const float* __restrict__ emb) {
    int i = blockIdx.x * blockDim.x + threadIdx.x;
    if (i >= LSEQ * DM) return;
    int l = i / DM, d = i - l * DM;
    g_x[i] = emb[(size_t)ids[l] * DM + d];
}

// rmsnorm fused with bf16 hi/lo split output
__global__ void rmsnorm_kernel(const float* __restrict__ w) {
    int l = blockIdx.x;
    const float* xr = &g_x[(size_t)l * DM];
    float s = 0.f;
    for (int d = threadIdx.x; d < DM; d += 256) {
        float v = xr[d];
        s += v * v;
    }
    __shared__ float red[8];
    #pragma unroll
    for (int o = 16; o; o >>= 1) s += __shfl_xor_sync(0xffffffffu, s, o);
    if ((threadIdx.x & 31) == 0) red[threadIdx.x >> 5] = s;
    __syncthreads();
    if (threadIdx.x < 8) {
        float t = red[threadIdx.x];
        #pragma unroll
        for (int o = 4; o; o >>= 1) t += __shfl_xor_sync(0xffu, t, o);
        if (threadIdx.x == 0) red[0] = rsqrtf(t / (float)DM + 1e-5f);
    }
    __syncthreads();
    float rinv = red[0];
    for (int d = threadIdx.x; d < DM; d += 256) {
        float v = xr[d] * rinv * w[d];
        __nv_bfloat16 hi = __float2bfloat16(v);
        __nv_bfloat16 lo = __float2bfloat16(v - __bfloat162float(hi));
        g_xn_hi[(size_t)l * DM + d] = hi;
        g_xn_lo[(size_t)l * DM + d] = lo;
    }
}

// transpose+split weights: W fp32 [K][N] -> hi/lo bf16 [N][K], bounds-checked in N
__global__ void wconv_kernel(const float* __restrict__ W,
                             __nv_bfloat16* __restrict__ hi,
                             __nv_bfloat16* __restrict__ lo, int K, int N) {
    __shared__ float t[32][33];
    int k0 = blockIdx.x * 32, n0 = blockIdx.y * 32;
    #pragma unroll
    for (int i = 0; i < 4; i++) {
        int n = n0 + threadIdx.x;
        t[threadIdx.y + i * 8][threadIdx.x] = (n < N) ?
            W[(size_t)(k0 + threadIdx.y + i * 8) * N + n] : 0.f;
    }
    __syncthreads();
    #pragma unroll
    for (int i = 0; i < 4; i++) {
        int n = n0 + threadIdx.y + i * 8;
        if (n >= N) continue;
        float v = t[threadIdx.x][threadIdx.y + i * 8];
        __nv_bfloat16 h = __float2bfloat16(v);
        __nv_bfloat16 l = __float2bfloat16(v - __bfloat162float(h));
        size_t idx = (size_t)n * K + k0 + threadIdx.x;
        hi[idx] = h;
        lo[idx] = l;
    }
}

// conv + silu, emits fp32 (for scan) and bf16 hi/lo (for x_proj GEMM)
__global__ void conv_silu_kernel(const float* __restrict__ w,
                                 const float* __restrict__ b) {
    int i = blockIdx.x * blockDim.x + threadIdx.x;
    if (i >= LSEQ * DI) return;
    int l = i / DI, d = i - l * DI;
    float s = b[d];
    #pragma unroll
    for (int k = 0; k < DCONV; k++) {
        int ll = l - (DCONV - 1) + k;
        if (ll >= 0) s = fmaf(w[d * DCONV + k], g_xz[(size_t)ll * DXZ + d], s);
    }
    float sig = 1.f / (1.f + __expf(-s));
    float v = s * sig;
    g_xr[i] = v;
    __nv_bfloat16 hi = __float2bfloat16(v);
    __nv_bfloat16 lo = __float2bfloat16(v - __bfloat162float(hi));
    g_xr_hi[i] = hi;
    g_xr_lo[i] = lo;
}

// ---------------- SIMT fp32 GEMM (dt_proj only: K=48) ----------------
__global__ void gemm_dt_proj_kernel(const float* __restrict__ W,
                                    const float* __restrict__ bias) {
    __shared__ float sA[16][65];
    __shared__ float sB[16][64];
    int tid = threadIdx.x;
    int tx = tid & 15, ty = tid >> 4;
    int row0 = blockIdx.y * 64;
    int col0 = blockIdx.x * 64;
    float acc[4][4] = {};
    for (int k0 = 0; k0 < DTR; k0 += 16) {
        {
            int m  = tid >> 2;
            int k4 = (tid & 3) * 4;
            const float4 v = *reinterpret_cast<const float4*>(
                &g_xdbl[(size_t)(row0 + m) * XDBL + k0 + k4]);
            sA[k4 + 0][m] = v.x; sA[k4 + 1][m] = v.y;
            sA[k4 + 2][m] = v.z; sA[k4 + 3][m] = v.w;
        }
        #pragma unroll
        for (int i = 0; i < 4; i++) {
            int idx = tid + i * 256;
            int k = idx >> 6, n = idx & 63;
            sB[k][n] = W[(size_t)(k0 + k) * DI + col0 + n];
        }
        __syncthreads();
        #pragma unroll
        for (int kk = 0; kk < 16; kk++) {
            float ra[4], rb[4];
            #pragma unroll
            for (int i = 0; i < 4; i++) ra[i] = sA[kk][ty * 4 + i];
            #pragma unroll
            for (int j = 0; j < 4; j++) rb[j] = sB[kk][tx * 4 + j];
            #pragma unroll
            for (int i = 0; i < 4; i++)
                #pragma unroll
                for (int j = 0; j < 4; j++)
                    acc[i][j] = fmaf(ra[i], rb[j], acc[i][j]);
        }
        __syncthreads();
    }
    #pragma unroll
    for (int i = 0; i < 4; i++) {
        int m = row0 + ty * 4 + i;
        #pragma unroll
        for (int j = 0; j < 4; j++) {
            int n = col0 + tx * 4 + j;
            float v = acc[i][j] + bias[n];
            v = (v > 20.f) ? v : log1pf(__expf(v));
            g_delta[(size_t)m * DI + n] = v;
        }
    }
}

// ---------------- chunked selective scan (power-chain exp) ----------------
__global__ void scan_phaseA_kernel(const float* __restrict__ A_log) {
    int d = blockIdx.x * blockDim.x + threadIdx.x;
    int chunk = blockIdx.y;
    __shared__ float sB[CLEN][DS];
    int l0 = chunk * CLEN;
    for (int idx = threadIdx.x; idx < CLEN * DS; idx += blockDim.x) {
        int l = idx >> 4, n = idx & 15;
        sB[l][n] = g_xdbl[(size_t)(l0 + l) * XDBL + DTR + n];
    }
    __syncthreads();

    float Arow[DS], h[DS], P[DS];
    bool chain = true;
    #pragma unroll
    for (int n = 0; n < DS; n++) {
        Arow[n] = -__expf(A_log[(size_t)d * DS + n]);
        h[n] = 0.f; P[n] = 1.f;
    }
    float r0 = Arow[0];
    #pragma unroll
    for (int n = 1; n < DS; n++)
        chain = chain && (fabsf(Arow[n] - (float)(n + 1) * r0)
                          <= 1e-5f * fabsf(Arow[n]) + 1e-7f);

    if (chain) {
        for (int l = 0; l < CLEN; l++) {
            float dl = g_delta[(size_t)(l0 + l) * DI + d];
            float du = dl * g_xr[(size_t)(l0 + l) * DI + d];
            float q = __expf(dl * r0);
            float a = 1.f;
            #pragma unroll
            for (int n = 0; n < DS; n++) {
                a *= q;
                h[n] = fmaf(a, h[n], du * sB[l][n]);
                P[n] *= a;
            }
        }
    } else {
        for (int l = 0; l < CLEN; l++) {
            float dl = g_delta[(size_t)(l0 + l) * DI + d];
            float du = dl * g_xr[(size_t)(l0 + l) * DI + d];
            #pragma unroll
            for (int n = 0; n < DS; n++) {
                float a = __expf(dl * Arow[n]);
                h[n] = fmaf(a, h[n], du * sB[l][n]);
                P[n] *= a;
            }
        }
    }
    size_t base = ((size_t)chunk * DI + d) * DS;
    #pragma unroll
    for (int n = 0; n < DS; n++) {
        g_Aprod[base + n] = P[n];
        g_Hend [base + n] = h[n];
    }
}

__global__ void scan_phaseB_kernel() {
    int i = blockIdx.x * blockDim.x + threadIdx.x;
    if (i >= DI * DS) return;
    float run = 0.f;
    #pragma unroll
    for (int c = 0; c < NCH; c++) {
        size_t idx = (size_t)c * DI * DS + i;
        g_Hinit[idx] = run;
        run = fmaf(g_Aprod[idx], run, g_Hend[idx]);
    }
}

__global__ void scan_phaseC_kernel(const float* __restrict__ A_log,
                                   const float* __restrict__ Dp) {
    int d = blockIdx.x * blockDim.x + threadIdx.x;
    int chunk = blockIdx.y;
    __shared__ float sB[CLEN][DS];
    __shared__ float sC[CLEN][DS];
    int l0 = chunk * CLEN;
    for (int idx = threadIdx.x; idx < CLEN * DS; idx += blockDim.x) {
        int l = idx >> 4, n = idx & 15;
        sB[l][n] = g_xdbl[(size_t)(l0 + l) * XDBL + DTR + n];
        sC[l][n] = g_xdbl[(size_t)(l0 + l) * XDBL + DTR + DS + n];
    }
    __syncthreads();

    float Arow[DS], h[DS];
    bool chain = true;
    size_t base = ((size_t)chunk * DI + d) * DS;
    #pragma unroll
    for (int n = 0; n < DS; n++) {
        Arow[n] = -__expf(A_log[(size_t)d * DS + n]);
        h[n] = g_Hinit[base + n];
    }
    float r0 = Arow[0];
    #pragma unroll
    for (int n = 1; n < DS; n++)
        chain = chain && (fabsf(Arow[n] - (float)(n + 1) * r0)
                          <= 1e-5f * fabsf(Arow[n]) + 1e-7f);
    float Dd = Dp[d];

    for (int l = 0; l < CLEN; l++) {
        float dl = g_delta[(size_t)(l0 + l) * DI + d];
        float u  = g_xr[(size_t)(l0 + l) * DI + d];
        float du = dl * u;
        float y = 0.f;
        if (chain) {
            float q = __expf(dl * r0);
            float a = 1.f;
            #pragma unroll
            for (int n = 0; n < DS; n++) {
                a *= q;
                h[n] = fmaf(a, h[n], du * sB[l][n]);
                y = fmaf(h[n], sC[l][n], y);
            }
        } else {
            #pragma unroll
            for (int n = 0; n < DS; n++) {
                float a = __expf(dl * Arow[n]);
                h[n] = fmaf(a, h[n], du * sB[l][n]);
                y = fmaf(h[n], sC[l][n], y);
            }
        }
        y = fmaf(u, Dd, y);
        float res = g_xz[(size_t)(l0 + l) * DXZ + DI + d];
        float sig = 1.f / (1.f + __expf(-res));
        float ya = y * (res * sig);
        __nv_bfloat16 hi = __float2bfloat16(ya);
        __nv_bfloat16 lo = __float2bfloat16(ya - __bfloat162float(hi));
        g_ya_hi[(size_t)(l0 + l) * DI + d] = hi;
        g_ya_lo[(size_t)(l0 + l) * DI + d] = lo;
    }
}

// ---------------- launcher ----------------
extern "C" void kernel_launch(void* const* d_in, const int* in_sizes, int n_in,
                              void* d_out, int out_size) {
    const int*   ids        = (const int*)  d_in[0];
    const float* emb        = (const float*)d_in[1];
    const float* norm_w     = (const float*)d_in[2];
    const float* in_proj_w  = (const float*)d_in[3];
    const float* conv_w     = (const float*)d_in[4];
    const float* conv_b     = (const float*)d_in[5];
    const float* x_proj_w   = (const float*)d_in[6];
    const float* dt_proj_w  = (const float*)d_in[7];
    const float* dt_proj_b  = (const float*)d_in[8];
    const float* A_log      = (const float*)d_in[9];
    const float* Dp         = (const float*)d_in[10];
    const float* out_proj_w = (const float*)d_in[11];
    float* out = (float*)d_out;

    cudaFuncSetAttribute(gemm_mma3_kernel,
                         cudaFuncAttributeMaxDynamicSharedMemorySize, SMEM_MMA);

    // resolve device-global scratch pointers
    __nv_bfloat16 *xn_hi, *xn_lo, *xr_hi, *xr_lo, *ya_hi, *ya_lo;
    __nv_bfloat16 *wt_hi, *wt_lo, *wxp_hi, *wxp_lo;
    float *xz, *x_res, *part;
    cudaGetSymbolAddress((void**)&xn_hi, g_xn_hi);
    cudaGetSymbolAddress((void**)&xn_lo, g_xn_lo);
    cudaGetSymbolAddress((void**)&xr_hi, g_xr_hi);
    cudaGetSymbolAddress((void**)&xr_lo, g_xr_lo);
    cudaGetSymbolAddress((void**)&ya_hi, g_ya_hi);
    cudaGetSymbolAddress((void**)&ya_lo, g_ya_lo);
    cudaGetSymbolAddress((void**)&wt_hi, g_wt_hi);
    cudaGetSymbolAddress((void**)&wt_lo, g_wt_lo);
    cudaGetSymbolAddress((void**)&wxp_hi, g_wxp_hi);
    cudaGetSymbolAddress((void**)&wxp_lo, g_wxp_lo);
    cudaGetSymbolAddress((void**)&xz,    g_xz);
    cudaGetSymbolAddress((void**)&x_res, g_x);
    cudaGetSymbolAddress((void**)&part,  g_part);

    embed_kernel<<<(LSEQ * DM + 255) / 256, 256>>>(ids, emb);

    for (int layer = 0; layer < NLAYER; layer++) {
        rmsnorm_kernel<<<LSEQ, 256>>>(norm_w + (size_t)layer * DM);

        // in_proj: [2048,768] @ [768,3072]  (single K, direct write)
        wconv_kernel<<<dim3(DM / 32, DXZ / 32), dim3(32, 8)>>>(
            in_proj_w + (size_t)layer * DM * DXZ, wt_hi, wt_lo, DM, DXZ);
        gemm_mma3_kernel<<<dim3(DXZ / 128, LSEQ / 128, 1), 256, SMEM_MMA>>>(
            xn_hi, xn_lo, wt_hi, wt_lo, xz, DM, DM, DXZ, DXZ);

        conv_silu_kernel<<<(LSEQ * DI + 255) / 256, 256>>>(
            conv_w + (size_t)layer * DI * DCONV,
            conv_b + (size_t)layer * DI);

        // x_proj: [2048,1536] @ [1536,80] via split-K 8 + reduce
        wconv_kernel<<<dim3(DI / 32, (XDBL + 31) / 32), dim3(32, 8)>>>(
            x_proj_w + (size_t)layer * DI * XDBL, wxp_hi, wxp_lo, DI, XDBL);
        gemm_mma3_kernel<<<dim3(1, LSEQ / 128, 8), 256, SMEM_MMA>>>(
            xr_hi, xr_lo, wxp_hi, wxp_lo, part, DI, DI / 8, XDBL, XDBL);
        xproj_reduce_kernel<<<(LSEQ * XDBL + 255) / 256, 256>>>();

        gemm_dt_proj_kernel<<<dim3(DI / 64, LSEQ / 64), 256>>>(
            dt_proj_w + (size_t)layer * DTR * DI,
            dt_proj_b + (size_t)layer * DI);

        scan_phaseA_kernel<<<dim3(DI / 128, NCH), 128>>>(
            A_log + (size_t)layer * DI * DS);
        scan_phaseB_kernel<<<(DI * DS + 255) / 256, 256>>>();
        scan_phaseC_kernel<<<dim3(DI / 128, NCH), 128>>>(
            A_log + (size_t)layer * DI * DS,
            Dp + (size_t)layer * DI);

        // out_proj: [2048,1536] @ [1536,768] via split-K 3 + residual reduce
        wconv_kernel<<<dim3(DI / 32, DM / 32), dim3(32, 8)>>>(
            out_proj_w + (size_t)layer * DI * DM, wt_hi, wt_lo, DI, DM);
        gemm_mma3_kernel<<<dim3(DM / 128, LSEQ / 128, 3), 256, SMEM_MMA>>>(
            ya_hi, ya_lo, wt_hi, wt_lo, part, DI, DI / 3, DM, DM);
        float* dest = (layer == NLAYER - 1) ? out : x_res;
        outproj_reduce_kernel<<<(LSEQ * DM + 255) / 256, 256>>>(dest);
    }
}

// round 5
// speedup vs baseline: 3.0891x; 1.3632x over previous
#include <cuda_runtime.h>
#include <cuda_bf16.h>
#include <cuda_fp16.h>
#include <math.h>
#include <stdint.h>

// ---------------- problem constants ----------------
#define LSEQ   2048
#define DM     768
#define DI     1536          // 2*DM
#define DXZ    3072          // 2*DI
#define DTR    48
#define DS     16
#define DCONV  4
#define NLAYER 2
#define XDBL   80            // DTR + 2*DS
#define NCH    128
#define CLEN   16            // LSEQ / NCH

// ---------------- scratch (device globals, no allocation) ----------------
__device__ __align__(16) float g_x   [LSEQ * DM];    // residual stream
__device__ __align__(16) float g_xz  [LSEQ * DXZ];   // in_proj output (xr | res)
__device__ __align__(16) float g_xr  [LSEQ * DI];    // conv+silu output (fp32 for scan)
__device__ __align__(16) float g_xdbl[LSEQ * XDBL];  // x_proj output (dt | B | C)
__device__ __align__(16) float g_delta[LSEQ * DI];   // softplus(dt@dt_proj + b)
__device__ __align__(16) float g_Aprod[NCH * DI * DS];
__device__ __align__(16) float g_Hend [NCH * DI * DS];
__device__ __align__(16) float g_Hinit[NCH * DI * DS];

// fp16 hi/lo split activations for tensor-core GEMMs
__device__ __align__(16) __half g_xn_hi[LSEQ * DM];
__device__ __align__(16) __half g_xn_lo[LSEQ * DM];
__device__ __align__(16) __half g_xr_hi[LSEQ * DI];
__device__ __align__(16) __half g_xr_lo[LSEQ * DI];
__device__ __align__(16) __half g_ya_hi[LSEQ * DI];
__device__ __align__(16) __half g_ya_lo[LSEQ * DI];
__device__ __align__(16) __half g_dt_hi[LSEQ * 64];   // dt cols padded 48->64
__device__ __align__(16) __half g_dt_lo[LSEQ * 64];
// fp16 weights, transposed [N][K] (hi only)
__device__ __align__(16) __half g_wt [DM * DXZ];      // in_proj / out_proj
__device__ __align__(16) __half g_wxp[128 * DI];      // x_proj [80->128 pad][1536]
__device__ __align__(16) __half g_wdt[DI * 64];       // dt_proj [1536][48->64 pad]
// split-K partials
__device__ __align__(16) float g_part[3 * LSEQ * DM];

// ---------------- small helpers ----------------
__device__ __forceinline__ uint32_t smem_u32(const void* p) {
    uint32_t a;
    asm("{ .reg .u64 t; cvta.to.shared.u64 t, %1; cvt.u32.u64 %0, t; }"
        : "=r"(a) : "l"(p));
    return a;
}
__device__ __forceinline__ void ldm4(uint32_t addr, uint32_t r[4]) {
    asm volatile("ldmatrix.sync.aligned.m8n8.x4.shared.b16 {%0,%1,%2,%3}, [%4];"
                 : "=r"(r[0]), "=r"(r[1]), "=r"(r[2]), "=r"(r[3]) : "r"(addr));
}
__device__ __forceinline__ void mma16816(float c[4], const uint32_t a[4],
                                         const uint32_t b0, const uint32_t b1) {
    asm volatile(
        "mma.sync.aligned.m16n8k16.row.col.f32.f16.f16.f32 "
        "{%0,%1,%2,%3}, {%4,%5,%6,%7}, {%8,%9}, {%0,%1,%2,%3};"
        : "+f"(c[0]), "+f"(c[1]), "+f"(c[2]), "+f"(c[3])
        : "r"(a[0]), "r"(a[1]), "r"(a[2]), "r"(a[3]), "r"(b0), "r"(b1));
}
__device__ __forceinline__ void h2split(float v, __half* hi, __half* lo) {
    __half h = __float2half(v);
    *hi = h;
    *lo = __float2half(v - __half2float(h));
}

// ---------------- fp16 2-term GEMM via mma.sync, 3-stage pipeline ----------------
// C[2048,N] = (Ah+Al)[2048,K] @ Bh^T with Bh as [N][K] row-major fp16.
// Tile 128x128, K-slab 32, 3 stages x 3 tiles (Ah,Al,Bh), 2 CTAs/SM.
// Split-K over blockIdx.z (ksize cols each); partial z writes C + z*2048*ldc.
#define SROW    40                       // 32 halfs + 8 pad
#define TILE_E  (128 * SROW)             // 5120 halfs = 10240 B
#define NSTAGE  3
#define SMEM_MMA (NSTAGE * 3 * TILE_E * 2)   // 92160 B

__device__ __forceinline__ void mma_load_stage(
        uint32_t smb, int stage,
        const __half* __restrict__ Ah, const __half* __restrict__ Al,
        const __half* __restrict__ Bh,
        int row0, int col0, int k0, int K, int tid) {
    #pragma unroll
    for (int t = 0; t < 3; t++) {
        const __half* src = (t == 0) ? Ah : (t == 1) ? Al : Bh;
        int r0 = (t < 2) ? row0 : col0;
        #pragma unroll
        for (int i = 0; i < 2; i++) {
            int c = tid + i * 256;
            int row = c >> 2, kc = (c & 3) * 8;
            uint32_t dst = smb + (uint32_t)(((stage * 3 + t) * TILE_E) + row * SROW + kc) * 2u;
            const void* gsrc = src + (size_t)(r0 + row) * K + k0 + kc;
            asm volatile("cp.async.cg.shared.global [%0], [%1], 16;"
                         :: "r"(dst), "l"(gsrc));
        }
    }
}

// MODE 0: plain write   MODE 1: softplus(v + bias[n])
template<int MODE>
__global__ void __launch_bounds__(256, 2)
gemm_fp16_kernel(const __half* __restrict__ Ahg, const __half* __restrict__ Alg,
                 const __half* __restrict__ Bhg,
                 float* __restrict__ C, const float* __restrict__ bias,
                 int K, int ksize, int ldc, int Nvalid) {
    extern __shared__ __half sm[];
    const int tid = threadIdx.x, lane = tid & 31, wid = tid >> 5;
    const int wm = wid & 3, wn = wid >> 2;         // 4 m-warps x 2 n-warps
    const int row0 = blockIdx.y * 128, col0 = blockIdx.x * 128;
    const int kb = blockIdx.z * ksize;
    C += (size_t)blockIdx.z * LSEQ * ldc;
    uint32_t smb = smem_u32(sm);

    float acc[2][8][4] = {};
    const int S = ksize / 32;

    mma_load_stage(smb, 0, Ahg, Alg, Bhg, row0, col0, kb, K, tid);
    asm volatile("cp.async.commit_group;" ::: "memory");
    mma_load_stage(smb, 1, Ahg, Alg, Bhg, row0, col0, kb + 32, K, tid);
    asm volatile("cp.async.commit_group;" ::: "memory");

    const int lrow = lane & 15, lcol = (lane >> 4) * 8;

    for (int s = 0; s < S; s++) {
        if (s + 2 < S)
            mma_load_stage(smb, (s + 2) % NSTAGE, Ahg, Alg, Bhg,
                           row0, col0, kb + (s + 2) * 32, K, tid);
        asm volatile("cp.async.commit_group;" ::: "memory");
        asm volatile("cp.async.wait_group 2;" ::: "memory");
        __syncthreads();

        int st = s % NSTAGE;
        uint32_t bAh = smb + (uint32_t)((st * 3 + 0) * TILE_E) * 2u;
        uint32_t bAl = smb + (uint32_t)((st * 3 + 1) * TILE_E) * 2u;
        uint32_t bBh = smb + (uint32_t)((st * 3 + 2) * TILE_E) * 2u;

        #pragma unroll
        for (int kk = 0; kk < 32; kk += 16) {
            uint32_t ah[2][4], al[2][4];
            #pragma unroll
            for (int mt = 0; mt < 2; mt++) {
                uint32_t off = (uint32_t)((wm * 32 + mt * 16 + lrow) * SROW + kk + lcol) * 2u;
                ldm4(bAh + off, ah[mt]);
                ldm4(bAl + off, al[mt]);
            }
            #pragma unroll
            for (int g = 0; g < 4; g++) {
                uint32_t b4h[4];
                uint32_t off = (uint32_t)((wn * 64 + g * 16 + lrow) * SROW + kk + lcol) * 2u;
                ldm4(bBh + off, b4h);
                #pragma unroll
                for (int mt = 0; mt < 2; mt++) {
                    mma16816(acc[mt][2 * g + 0], ah[mt], b4h[0], b4h[2]);
                    mma16816(acc[mt][2 * g + 0], al[mt], b4h[0], b4h[2]);
                    mma16816(acc[mt][2 * g + 1], ah[mt], b4h[1], b4h[3]);
                    mma16816(acc[mt][2 * g + 1], al[mt], b4h[1], b4h[3]);
                }
            }
        }
        __syncthreads();
    }

    // epilogue
    int gq = lane >> 2, tq = lane & 3;
    #pragma unroll
    for (int mt = 0; mt < 2; mt++) {
        #pragma unroll
        for (int n8 = 0; n8 < 8; n8++) {
            int rm = row0 + wm * 32 + mt * 16 + gq;
            int cn = col0 + wn * 64 + n8 * 8 + 2 * tq;
            if (cn >= Nvalid) continue;
            float v[4] = {acc[mt][n8][0], acc[mt][n8][1],
                          acc[mt][n8][2], acc[mt][n8][3]};
            if (MODE == 1) {
                float b0 = bias[cn], b1 = bias[cn + 1];
                v[0] += b0; v[1] += b1; v[2] += b0; v[3] += b1;
                #pragma unroll
                for (int q = 0; q < 4; q++)
                    v[q] = (v[q] > 20.f) ? v[q] : log1pf(__expf(v[q]));
            }
            *reinterpret_cast<float2*>(C + (size_t)rm * ldc + cn) =
                make_float2(v[0], v[1]);
            *reinterpret_cast<float2*>(C + (size_t)(rm + 8) * ldc + cn) =
                make_float2(v[2], v[3]);
        }
    }
}

// reduce 8 x_proj split-K partials -> g_xdbl, emit fp16 split of dt cols (pad 64)
__global__ void xproj_reduce_kernel() {
    int i = blockIdx.x * blockDim.x + threadIdx.x;
    if (i >= LSEQ * XDBL) return;
    float s = 0.f;
    #pragma unroll
    for (int z = 0; z < 8; z++) s += g_part[(size_t)z * LSEQ * XDBL + i];
    g_xdbl[i] = s;
    int l = i / XDBL, c = i - l * XDBL;
    if (c < 64) {
        // cols 48..63 multiply zero weight rows, value irrelevant
        h2split(s, &g_dt_hi[(size_t)l * 64 + c], &g_dt_lo[(size_t)l * 64 + c]);
    }
}

// reduce 3 out_proj split-K partials + residual -> dest
__global__ void outproj_reduce_kernel(float* __restrict__ dest) {
    int i = blockIdx.x * blockDim.x + threadIdx.x;
    if (i >= LSEQ * DM) return;
    float s = g_x[i];
    #pragma unroll
    for (int z = 0; z < 3; z++) s += g_part[(size_t)z * LSEQ * DM + i];
    dest[i] = s;
}

// ---------------- elementwise kernels ----------------
__global__ void embed_kernel(const int* __restrict__ ids,
                             const float* __restrict__ emb) {
    int i = blockIdx.x * blockDim.x + threadIdx.x;
    if (i >= LSEQ * DM) return;
    int l = i / DM, d = i - l * DM;
    g_x[i] = emb[(size_t)ids[l] * DM + d];
}

// rmsnorm fused with fp16 hi/lo split output
__global__ void rmsnorm_kernel(const float* __restrict__ w) {
    int l = blockIdx.x;
    const float* xr = &g_x[(size_t)l * DM];
    float s = 0.f;
    for (int d = threadIdx.x; d < DM; d += 256) {
        float v = xr[d];
        s += v * v;
    }
    __shared__ float red[8];
    #pragma unroll
    for (int o = 16; o; o >>= 1) s += __shfl_xor_sync(0xffffffffu, s, o);
    if ((threadIdx.x & 31) == 0) red[threadIdx.x >> 5] = s;
    __syncthreads();
    if (threadIdx.x < 8) {
        float t = red[threadIdx.x];
        #pragma unroll
        for (int o = 4; o; o >>= 1) t += __shfl_xor_sync(0xffu, t, o);
        if (threadIdx.x == 0) red[0] = rsqrtf(t / (float)DM + 1e-5f);
    }
    __syncthreads();
    float rinv = red[0];
    for (int d = threadIdx.x; d < DM; d += 256) {
        float v = xr[d] * rinv * w[d];
        h2split(v, &g_xn_hi[(size_t)l * DM + d], &g_xn_lo[(size_t)l * DM + d]);
    }
}

// transpose weights: W fp32 [Kin][N] -> fp16 [n][k] for n<Npad, k<Kpad
// (zero outside true dims)
__global__ void wconv_kernel(const float* __restrict__ W, __half* __restrict__ out,
                             int Kin, int Kpad, int N, int Npad) {
    __shared__ float t[32][33];
    int k0 = blockIdx.x * 32, n0 = blockIdx.y * 32;
    #pragma unroll
    for (int i = 0; i < 4; i++) {
        int k = k0 + threadIdx.y + i * 8;
        int n = n0 + threadIdx.x;
        t[threadIdx.y + i * 8][threadIdx.x] =
            (k < Kin && n < N) ? W[(size_t)k * N + n] : 0.f;
    }
    __syncthreads();
    #pragma unroll
    for (int i = 0; i < 4; i++) {
        int n = n0 + threadIdx.y + i * 8;
        int k = k0 + threadIdx.x;
        if (n < Npad && k < Kpad)
            out[(size_t)n * Kpad + k] = __float2half(t[threadIdx.x][threadIdx.y + i * 8]);
    }
}

// conv + silu, emits fp32 (for scan) and fp16 hi/lo (for x_proj GEMM)
__global__ void conv_silu_kernel(const float* __restrict__ w,
                                 const float* __restrict__ b) {
    int i = blockIdx.x * blockDim.x + threadIdx.x;
    if (i >= LSEQ * DI) return;
    int l = i / DI, d = i - l * DI;
    float s = b[d];
    #pragma unroll
    for (int k = 0; k < DCONV; k++) {
        int ll = l - (DCONV - 1) + k;
        if (ll >= 0) s = fmaf(w[d * DCONV + k], g_xz[(size_t)ll * DXZ + d], s);
    }
    float sig = 1.f / (1.f + __expf(-s));
    float v = s * sig;
    g_xr[i] = v;
    h2split(v, &g_xr_hi[i], &g_xr_lo[i]);
}

// ---------------- chunked selective scan (power-chain exp) ----------------
__global__ void scan_phaseA_kernel(const float* __restrict__ A_log) {
    int d = blockIdx.x * blockDim.x + threadIdx.x;
    int chunk = blockIdx.y;
    __shared__ float sB[CLEN][DS];
    int l0 = chunk * CLEN;
    for (int idx = threadIdx.x; idx < CLEN * DS; idx += blockDim.x) {
        int l = idx >> 4, n = idx & 15;
        sB[l][n] = g_xdbl[(size_t)(l0 + l) * XDBL + DTR + n];
    }
    __syncthreads();

    float Arow[DS], h[DS], P[DS];
    bool chain = true;
    #pragma unroll
    for (int n = 0; n < DS; n++) {
        Arow[n] = -__expf(A_log[(size_t)d * DS + n]);
        h[n] = 0.f; P[n] = 1.f;
    }
    float r0 = Arow[0];
    #pragma unroll
    for (int n = 1; n < DS; n++)
        chain = chain && (fabsf(Arow[n] - (float)(n + 1) * r0)
                          <= 1e-5f * fabsf(Arow[n]) + 1e-7f);

    if (chain) {
        #pragma unroll
        for (int l = 0; l < CLEN; l++) {
            float dl = g_delta[(size_t)(l0 + l) * DI + d];
            float du = dl * g_xr[(size_t)(l0 + l) * DI + d];
            float q = __expf(dl * r0);
            float a = 1.f;
            #pragma unroll
            for (int n = 0; n < DS; n++) {
                a *= q;
                h[n] = fmaf(a, h[n], du * sB[l][n]);
                P[n] *= a;
            }
        }
    } else {
        for (int l = 0; l < CLEN; l++) {
            float dl = g_delta[(size_t)(l0 + l) * DI + d];
            float du = dl * g_xr[(size_t)(l0 + l) * DI + d];
            #pragma unroll
            for (int n = 0; n < DS; n++) {
                float a = __expf(dl * Arow[n]);
                h[n] = fmaf(a, h[n], du * sB[l][n]);
                P[n] *= a;
            }
        }
    }
    size_t base = ((size_t)chunk * DI + d) * DS;
    #pragma unroll
    for (int n = 0; n < DS; n++) {
        g_Aprod[base + n] = P[n];
        g_Hend [base + n] = h[n];
    }
}

__global__ void scan_phaseB_kernel() {
    int i = blockIdx.x * blockDim.x + threadIdx.x;
    if (i >= DI * DS) return;
    float run = 0.f;
    #pragma unroll 8
    for (int c = 0; c < NCH; c++) {
        size_t idx = (size_t)c * DI * DS + i;
        g_Hinit[idx] = run;
        run = fmaf(g_Aprod[idx], run, g_Hend[idx]);
    }
}

__global__ void scan_phaseC_kernel(const float* __restrict__ A_log,
                                   const float* __restrict__ Dp) {
    int d = blockIdx.x * blockDim.x + threadIdx.x;
    int chunk = blockIdx.y;
    __shared__ float sB[CLEN][DS];
    __shared__ float sC[CLEN][DS];
    int l0 = chunk * CLEN;
    for (int idx = threadIdx.x; idx < CLEN * DS; idx += blockDim.x) {
        int l = idx >> 4, n = idx & 15;
        sB[l][n] = g_xdbl[(size_t)(l0 + l) * XDBL + DTR + n];
        sC[l][n] = g_xdbl[(size_t)(l0 + l) * XDBL + DTR + DS + n];
    }
    __syncthreads();

    float Arow[DS], h[DS];
    bool chain = true;
    size_t base = ((size_t)chunk * DI + d) * DS;
    #pragma unroll
    for (int n = 0; n < DS; n++) {
        Arow[n] = -__expf(A_log[(size_t)d * DS + n]);
        h[n] = g_Hinit[base + n];
    }
    float r0 = Arow[0];
    #pragma unroll
    for (int n = 1; n < DS; n++)
        chain = chain && (fabsf(Arow[n] - (float)(n + 1) * r0)
                          <= 1e-5f * fabsf(Arow[n]) + 1e-7f);
    float Dd = Dp[d];

    for (int l = 0; l < CLEN; l++) {
        float dl = g_delta[(size_t)(l0 + l) * DI + d];
        float u  = g_xr[(size_t)(l0 + l) * DI + d];
        float du = dl * u;
        float y = 0.f;
        if (chain) {
            float q = __expf(dl * r0);
            float a = 1.f;
            #pragma unroll
            for (int n = 0; n < DS; n++) {
                a *= q;
                h[n] = fmaf(a, h[n], du * sB[l][n]);
                y = fmaf(h[n], sC[l][n], y);
            }
        } else {
            #pragma unroll
            for (int n = 0; n < DS; n++) {
                float a = __expf(dl * Arow[n]);
                h[n] = fmaf(a, h[n], du * sB[l][n]);
                y = fmaf(h[n], sC[l][n], y);
            }
        }
        y = fmaf(u, Dd, y);
        float res = g_xz[(size_t)(l0 + l) * DXZ + DI + d];
        float sig = 1.f / (1.f + __expf(-res));
        float ya = y * (res * sig);
        h2split(ya, &g_ya_hi[(size_t)(l0 + l) * DI + d],
                    &g_ya_lo[(size_t)(l0 + l) * DI + d]);
    }
}

// ---------------- launcher ----------------
extern "C" void kernel_launch(void* const* d_in, const int* in_sizes, int n_in,
                              void* d_out, int out_size) {
    const int*   ids        = (const int*)  d_in[0];
    const float* emb        = (const float*)d_in[1];
    const float* norm_w     = (const float*)d_in[2];
    const float* in_proj_w  = (const float*)d_in[3];
    const float* conv_w     = (const float*)d_in[4];
    const float* conv_b     = (const float*)d_in[5];
    const float* x_proj_w   = (const float*)d_in[6];
    const float* dt_proj_w  = (const float*)d_in[7];
    const float* dt_proj_b  = (const float*)d_in[8];
    const float* A_log      = (const float*)d_in[9];
    const float* Dp         = (const float*)d_in[10];
    const float* out_proj_w = (const float*)d_in[11];
    float* out = (float*)d_out;

    cudaFuncSetAttribute(gemm_fp16_kernel<0>,
                         cudaFuncAttributeMaxDynamicSharedMemorySize, SMEM_MMA);
    cudaFuncSetAttribute(gemm_fp16_kernel<1>,
                         cudaFuncAttributeMaxDynamicSharedMemorySize, SMEM_MMA);

    // resolve device-global scratch pointers
    __half *xn_hi, *xn_lo, *xr_hi, *xr_lo, *ya_hi, *ya_lo, *dt_hi, *dt_lo;
    __half *wt, *wxp, *wdt;
    float *xz, *x_res, *part, *delta;
    cudaGetSymbolAddress((void**)&xn_hi, g_xn_hi);
    cudaGetSymbolAddress((void**)&xn_lo, g_xn_lo);
    cudaGetSymbolAddress((void**)&xr_hi, g_xr_hi);
    cudaGetSymbolAddress((void**)&xr_lo, g_xr_lo);
    cudaGetSymbolAddress((void**)&ya_hi, g_ya_hi);
    cudaGetSymbolAddress((void**)&ya_lo, g_ya_lo);
    cudaGetSymbolAddress((void**)&dt_hi, g_dt_hi);
    cudaGetSymbolAddress((void**)&dt_lo, g_dt_lo);
    cudaGetSymbolAddress((void**)&wt,    g_wt);
    cudaGetSymbolAddress((void**)&wxp,   g_wxp);
    cudaGetSymbolAddress((void**)&wdt,   g_wdt);
    cudaGetSymbolAddress((void**)&xz,    g_xz);
    cudaGetSymbolAddress((void**)&x_res, g_x);
    cudaGetSymbolAddress((void**)&part,  g_part);
    cudaGetSymbolAddress((void**)&delta, g_delta);

    embed_kernel<<<(LSEQ * DM + 255) / 256, 256>>>(ids, emb);

    for (int layer = 0; layer < NLAYER; layer++) {
        rmsnorm_kernel<<<LSEQ, 256>>>(norm_w + (size_t)layer * DM);

        // in_proj: [2048,768] @ [768,3072]
        wconv_kernel<<<dim3(DM / 32, DXZ / 32), dim3(32, 8)>>>(
            in_proj_w + (size_t)layer * DM * DXZ, wt, DM, DM, DXZ, DXZ);
        gemm_fp16_kernel<0><<<dim3(DXZ / 128, LSEQ / 128, 1), 256, SMEM_MMA>>>(
            xn_hi, xn_lo, wt, xz, nullptr, DM, DM, DXZ, DXZ);

        // dt_proj weights can convert early (independent)
        wconv_kernel<<<dim3(64 / 32, DI / 32), dim3(32, 8)>>>(
            dt_proj_w + (size_t)layer * DTR * DI, wdt, DTR, 64, DI, DI);

        conv_silu_kernel<<<(LSEQ * DI + 255) / 256, 256>>>(
            conv_w + (size_t)layer * DI * DCONV,
            conv_b + (size_t)layer * DI);

        // x_proj: [2048,1536] @ [1536,80] via split-K 8 + reduce
        wconv_kernel<<<dim3(DI / 32, 128 / 32), dim3(32, 8)>>>(
            x_proj_w + (size_t)layer * DI * XDBL, wxp, DI, DI, XDBL, 128);
        gemm_fp16_kernel<0><<<dim3(1, LSEQ / 128, 8), 256, SMEM_MMA>>>(
            xr_hi, xr_lo, wxp, part, nullptr, DI, DI / 8, XDBL, XDBL);
        xproj_reduce_kernel<<<(LSEQ * XDBL + 255) / 256, 256>>>();

        // dt_proj: [2048,64pad] @ [64pad,1536], softplus+bias epilogue
        gemm_fp16_kernel<1><<<dim3(DI / 128, LSEQ / 128, 1), 256, SMEM_MMA>>>(
            dt_hi, dt_lo, wdt, delta,
            dt_proj_b + (size_t)layer * DI, 64, 64, DI, DI);

        scan_phaseA_kernel<<<dim3(DI / 128, NCH), 128>>>(
            A_log + (size_t)layer * DI * DS);
        scan_phaseB_kernel<<<(DI * DS + 255) / 256, 256>>>();
        scan_phaseC_kernel<<<dim3(DI / 128, NCH), 128>>>(
            A_log + (size_t)layer * DI * DS,
            Dp + (size_t)layer * DI);

        // out_proj: [2048,1536] @ [1536,768] via split-K 3 + residual reduce
        wconv_kernel<<<dim3(DI / 32, DM / 32), dim3(32, 8)>>>(
            out_proj_w + (size_t)layer * DI * DM, wt, DI, DI, DM, DM);
        gemm_fp16_kernel<0><<<dim3(DM / 128, LSEQ / 128, 3), 256, SMEM_MMA>>>(
            ya_hi, ya_lo, wt, part, nullptr, DI, DI / 3, DM, DM);
        float* dest = (layer == NLAYER - 1) ? out : x_res;
        outproj_reduce_kernel<<<(LSEQ * DM + 255) / 256, 256>>>(dest);
    }
}

// round 6
// speedup vs baseline: 3.3399x; 1.0812x over previous
#include <cuda_runtime.h>
#include <cuda_fp16.h>
#include <math.h>
#include <stdint.h>

// ---------------- problem constants ----------------
#define LSEQ   2048
#define DM     768
#define DI     1536          // 2*DM
#define DXZ    3072          // 2*DI
#define DTR    48
#define DS     16
#define DCONV  4
#define NLAYER 2
#define XDBL   80            // DTR + 2*DS
#define NCH    128
#define CLEN   16            // LSEQ / NCH

// ---------------- scratch (device globals, no allocation) ----------------
__device__ __align__(16) float g_x   [LSEQ * DM];    // residual stream
__device__ __align__(16) float g_xz  [LSEQ * DXZ];   // in_proj output (xr | res)
__device__ __align__(16) float g_xr  [LSEQ * DI];    // conv+silu output (fp32 for scan)
__device__ __align__(16) float g_xdbl[LSEQ * XDBL];  // x_proj output (dt | B | C)
__device__ __align__(16) float g_delta[LSEQ * DI];   // softplus(dt@dt_proj + b)
__device__ __align__(16) float g_Aprod[NCH * DI * DS];
__device__ __align__(16) float g_Hend [NCH * DI * DS];
__device__ __align__(16) float g_Hinit[NCH * DI * DS];

// fp16 activations for tensor-core GEMMs
__device__ __align__(16) __half g_xn [LSEQ * DM];
__device__ __align__(16) __half g_xrh[LSEQ * DI];
__device__ __align__(16) __half g_ya [LSEQ * DI];
__device__ __align__(16) __half g_dt [LSEQ * 64];     // dt cols padded 48->64
// fp16 weights, transposed [N][K]
__device__ __align__(16) __half g_wt [DM * DXZ];      // in_proj / out_proj
__device__ __align__(16) __half g_wxp[128 * DI];      // x_proj [80->128 pad][1536]
__device__ __align__(16) __half g_wdt[DI * 64];       // dt_proj [1536][48->64 pad]
// split-K partials
__device__ __align__(16) float g_part[3 * LSEQ * DM];

// ---------------- small helpers ----------------
__device__ __forceinline__ uint32_t smem_u32(const void* p) {
    uint32_t a;
    asm("{ .reg .u64 t; cvta.to.shared.u64 t, %1; cvt.u32.u64 %0, t; }"
        : "=r"(a) : "l"(p));
    return a;
}
__device__ __forceinline__ void ldm4(uint32_t addr, uint32_t r[4]) {
    asm volatile("ldmatrix.sync.aligned.m8n8.x4.shared.b16 {%0,%1,%2,%3}, [%4];"
                 : "=r"(r[0]), "=r"(r[1]), "=r"(r[2]), "=r"(r[3]) : "r"(addr));
}
__device__ __forceinline__ void mma16816(float c[4], const uint32_t a[4],
                                         const uint32_t b0, const uint32_t b1) {
    asm volatile(
        "mma.sync.aligned.m16n8k16.row.col.f32.f16.f16.f32 "
        "{%0,%1,%2,%3}, {%4,%5,%6,%7}, {%8,%9}, {%0,%1,%2,%3};"
        : "+f"(c[0]), "+f"(c[1]), "+f"(c[2]), "+f"(c[3])
        : "r"(a[0]), "r"(a[1]), "r"(a[2]), "r"(a[3]), "r"(b0), "r"(b1));
}

// ---------------- single-term fp16 GEMM via mma.sync ----------------
// C[2048,N] = A[2048,K] @ B^T with B as [N][K] row-major fp16.
// Tile 128x128, K-slab 32, 3 stages x 2 tiles, 3 CTAs/SM, 1 sync/slab.
// Split-K over blockIdx.z (ksize cols each); partial z writes C + z*2048*ldc.
#define SROW    40                       // 32 halfs + 8 pad
#define TILE_E  (128 * SROW)             // 5120 halfs = 10240 B
#define NSTAGE  3
#define SMEM_MMA (NSTAGE * 2 * TILE_E * 2)   // 61440 B

__device__ __forceinline__ void mma_load_stage(
        uint32_t smb, int stage,
        const __half* __restrict__ A, const __half* __restrict__ B,
        int row0, int col0, int k0, int K, int tid) {
    #pragma unroll
    for (int t = 0; t < 2; t++) {
        const __half* src = (t == 0) ? A : B;
        int r0 = (t == 0) ? row0 : col0;
        #pragma unroll
        for (int i = 0; i < 2; i++) {
            int c = tid + i * 256;
            int row = c >> 2, kc = (c & 3) * 8;
            uint32_t dst = smb + (uint32_t)(((stage * 2 + t) * TILE_E) + row * SROW + kc) * 2u;
            const void* gsrc = src + (size_t)(r0 + row) * K + k0 + kc;
            asm volatile("cp.async.cg.shared.global [%0], [%1], 16;"
                         :: "r"(dst), "l"(gsrc));
        }
    }
    asm volatile("cp.async.commit_group;" ::: "memory");
}

// MODE 0: plain write   MODE 1: softplus(v + bias[n])
template<int MODE>
__global__ void __launch_bounds__(256, 3)
gemm_fp16_kernel(const __half* __restrict__ Ag, const __half* __restrict__ Bg,
                 float* __restrict__ C, const float* __restrict__ bias,
                 int K, int ksize, int ldc, int Nvalid) {
    extern __shared__ __half sm[];
    const int tid = threadIdx.x, lane = tid & 31, wid = tid >> 5;
    const int wm = wid & 3, wn = wid >> 2;         // 4 m-warps x 2 n-warps
    const int row0 = blockIdx.y * 128, col0 = blockIdx.x * 128;
    const int kb = blockIdx.z * ksize;
    C += (size_t)blockIdx.z * LSEQ * ldc;
    uint32_t smb = smem_u32(sm);

    float acc[2][8][4] = {};
    const int S = ksize / 32;

    mma_load_stage(smb, 0, Ag, Bg, row0, col0, kb, K, tid);
    mma_load_stage(smb, 1, Ag, Bg, row0, col0, kb + 32, K, tid);

    const int lrow = lane & 15, lcol = (lane >> 4) * 8;

    for (int s = 0; s < S; s++) {
        if (s + 1 < S) {
            asm volatile("cp.async.wait_group 1;" ::: "memory");
        } else {
            asm volatile("cp.async.wait_group 0;" ::: "memory");
        }
        __syncthreads();
        if (s + 2 < S)
            mma_load_stage(smb, (s + 2) % NSTAGE, Ag, Bg,
                           row0, col0, kb + (s + 2) * 32, K, tid);

        int st = s % NSTAGE;
        uint32_t bA = smb + (uint32_t)((st * 2 + 0) * TILE_E) * 2u;
        uint32_t bB = smb + (uint32_t)((st * 2 + 1) * TILE_E) * 2u;

        #pragma unroll
        for (int kk = 0; kk < 32; kk += 16) {
            uint32_t ah[2][4];
            #pragma unroll
            for (int mt = 0; mt < 2; mt++) {
                uint32_t off = (uint32_t)((wm * 32 + mt * 16 + lrow) * SROW + kk + lcol) * 2u;
                ldm4(bA + off, ah[mt]);
            }
            #pragma unroll
            for (int g = 0; g < 4; g++) {
                uint32_t b4[4];
                uint32_t off = (uint32_t)((wn * 64 + g * 16 + lrow) * SROW + kk + lcol) * 2u;
                ldm4(bB + off, b4);
                #pragma unroll
                for (int mt = 0; mt < 2; mt++) {
                    mma16816(acc[mt][2 * g + 0], ah[mt], b4[0], b4[2]);
                    mma16816(acc[mt][2 * g + 1], ah[mt], b4[1], b4[3]);
                }
            }
        }
    }

    // epilogue
    int gq = lane >> 2, tq = lane & 3;
    #pragma unroll
    for (int mt = 0; mt < 2; mt++) {
        #pragma unroll
        for (int n8 = 0; n8 < 8; n8++) {
            int rm = row0 + wm * 32 + mt * 16 + gq;
            int cn = col0 + wn * 64 + n8 * 8 + 2 * tq;
            if (cn >= Nvalid) continue;
            float v[4] = {acc[mt][n8][0], acc[mt][n8][1],
                          acc[mt][n8][2], acc[mt][n8][3]};
            if (MODE == 1) {
                float b0 = bias[cn], b1 = bias[cn + 1];
                v[0] += b0; v[1] += b1; v[2] += b0; v[3] += b1;
                #pragma unroll
                for (int q = 0; q < 4; q++)
                    v[q] = (v[q] > 20.f) ? v[q] : log1pf(__expf(v[q]));
            }
            *reinterpret_cast<float2*>(C + (size_t)rm * ldc + cn) =
                make_float2(v[0], v[1]);
            *reinterpret_cast<float2*>(C + (size_t)(rm + 8) * ldc + cn) =
                make_float2(v[2], v[3]);
        }
    }
}

// reduce 8 x_proj split-K partials -> g_xdbl, emit fp16 dt cols (pad 64)
__global__ void xproj_reduce_kernel() {
    int i = blockIdx.x * blockDim.x + threadIdx.x;
    if (i >= LSEQ * XDBL) return;
    float s = 0.f;
    #pragma unroll
    for (int z = 0; z < 8; z++) s += g_part[(size_t)z * LSEQ * XDBL + i];
    g_xdbl[i] = s;
    int l = i / XDBL, c = i - l * XDBL;
    if (c < 64) g_dt[(size_t)l * 64 + c] = __float2half(s);
}

// reduce 3 out_proj split-K partials + residual -> dest
__global__ void outproj_reduce_kernel(float* __restrict__ dest) {
    int i = blockIdx.x * blockDim.x + threadIdx.x;
    if (i >= LSEQ * DM) return;
    float s = g_x[i];
    #pragma unroll
    for (int z = 0; z < 3; z++) s += g_part[(size_t)z * LSEQ * DM + i];
    dest[i] = s;
}

// ---------------- elementwise kernels ----------------
__global__ void embed_kernel(const int* __restrict__ ids,
                             const float* __restrict__ emb) {
    int i = blockIdx.x * blockDim.x + threadIdx.x;
    if (i >= LSEQ * DM) return;
    int l = i / DM, d = i - l * DM;
    g_x[i] = emb[(size_t)ids[l] * DM + d];
}

// rmsnorm fused with fp16 output
__global__ void rmsnorm_kernel(const float* __restrict__ w) {
    int l = blockIdx.x;
    const float* xr = &g_x[(size_t)l * DM];
    float s = 0.f;
    for (int d = threadIdx.x; d < DM; d += 256) {
        float v = xr[d];
        s += v * v;
    }
    __shared__ float red[8];
    #pragma unroll
    for (int o = 16; o; o >>= 1) s += __shfl_xor_sync(0xffffffffu, s, o);
    if ((threadIdx.x & 31) == 0) red[threadIdx.x >> 5] = s;
    __syncthreads();
    if (threadIdx.x < 8) {
        float t = red[threadIdx.x];
        #pragma unroll
        for (int o = 4; o; o >>= 1) t += __shfl_xor_sync(0xffu, t, o);
        if (threadIdx.x == 0) red[0] = rsqrtf(t / (float)DM + 1e-5f);
    }
    __syncthreads();
    float rinv = red[0];
    for (int d = threadIdx.x; d < DM; d += 256)
        g_xn[(size_t)l * DM + d] = __float2half(xr[d] * rinv * w[d]);
}

// transpose weights: W fp32 [Kin][N] -> fp16 [n][k] for n<Npad, k<Kpad
// (zero outside true dims)
__global__ void wconv_kernel(const float* __restrict__ W, __half* __restrict__ out,
                             int Kin, int Kpad, int N, int Npad) {
    __shared__ float t[32][33];
    int k0 = blockIdx.x * 32, n0 = blockIdx.y * 32;
    #pragma unroll
    for (int i = 0; i < 4; i++) {
        int k = k0 + threadIdx.y + i * 8;
        int n = n0 + threadIdx.x;
        t[threadIdx.y + i * 8][threadIdx.x] =
            (k < Kin && n < N) ? W[(size_t)k * N + n] : 0.f;
    }
    __syncthreads();
    #pragma unroll
    for (int i = 0; i < 4; i++) {
        int n = n0 + threadIdx.y + i * 8;
        int k = k0 + threadIdx.x;
        if (n < Npad && k < Kpad)
            out[(size_t)n * Kpad + k] = __float2half(t[threadIdx.x][threadIdx.y + i * 8]);
    }
}

// conv + silu, emits fp32 (for scan) and fp16 (for x_proj GEMM)
__global__ void conv_silu_kernel(const float* __restrict__ w,
                                 const float* __restrict__ b) {
    int i = blockIdx.x * blockDim.x + threadIdx.x;
    if (i >= LSEQ * DI) return;
    int l = i / DI, d = i - l * DI;
    float s = b[d];
    #pragma unroll
    for (int k = 0; k < DCONV; k++) {
        int ll = l - (DCONV - 1) + k;
        if (ll >= 0) s = fmaf(w[d * DCONV + k], g_xz[(size_t)ll * DXZ + d], s);
    }
    float sig = 1.f / (1.f + __expf(-s));
    float v = s * sig;
    g_xr[i] = v;
    g_xrh[i] = __float2half(v);
}

// ---------------- chunked selective scan (power-chain exp) ----------------
__global__ void scan_phaseA_kernel(const float* __restrict__ A_log) {
    int d = blockIdx.x * blockDim.x + threadIdx.x;
    int chunk = blockIdx.y;
    __shared__ float sB[CLEN][DS];
    int l0 = chunk * CLEN;
    for (int idx = threadIdx.x; idx < CLEN * DS; idx += blockDim.x) {
        int l = idx >> 4, n = idx & 15;
        sB[l][n] = g_xdbl[(size_t)(l0 + l) * XDBL + DTR + n];
    }
    __syncthreads();

    float Arow[DS], h[DS], P[DS];
    bool chain = true;
    #pragma unroll
    for (int n = 0; n < DS; n++) {
        Arow[n] = -__expf(A_log[(size_t)d * DS + n]);
        h[n] = 0.f; P[n] = 1.f;
    }
    float r0 = Arow[0];
    #pragma unroll
    for (int n = 1; n < DS; n++)
        chain = chain && (fabsf(Arow[n] - (float)(n + 1) * r0)
                          <= 1e-5f * fabsf(Arow[n]) + 1e-7f);

    if (chain) {
        #pragma unroll
        for (int l = 0; l < CLEN; l++) {
            float dl = g_delta[(size_t)(l0 + l) * DI + d];
            float du = dl * g_xr[(size_t)(l0 + l) * DI + d];
            float q = __expf(dl * r0);
            float a = 1.f;
            #pragma unroll
            for (int n = 0; n < DS; n++) {
                a *= q;
                h[n] = fmaf(a, h[n], du * sB[l][n]);
                P[n] *= a;
            }
        }
    } else {
        for (int l = 0; l < CLEN; l++) {
            float dl = g_delta[(size_t)(l0 + l) * DI + d];
            float du = dl * g_xr[(size_t)(l0 + l) * DI + d];
            #pragma unroll
            for (int n = 0; n < DS; n++) {
                float a = __expf(dl * Arow[n]);
                h[n] = fmaf(a, h[n], du * sB[l][n]);
                P[n] *= a;
            }
        }
    }
    size_t base = ((size_t)chunk * DI + d) * DS;
    #pragma unroll
    for (int n = 0; n < DS; n++) {
        g_Aprod[base + n] = P[n];
        g_Hend [base + n] = h[n];
    }
}

__global__ void scan_phaseB_kernel() {
    int i = blockIdx.x * blockDim.x + threadIdx.x;
    if (i >= DI * DS) return;
    float run = 0.f;
    #pragma unroll 8
    for (int c = 0; c < NCH; c++) {
        size_t idx = (size_t)c * DI * DS + i;
        g_Hinit[idx] = run;
        run = fmaf(g_Aprod[idx], run, g_Hend[idx]);
    }
}

__global__ void scan_phaseC_kernel(const float* __restrict__ A_log,
                                   const float* __restrict__ Dp) {
    int d = blockIdx.x * blockDim.x + threadIdx.x;
    int chunk = blockIdx.y;
    __shared__ float sB[CLEN][DS];
    __shared__ float sC[CLEN][DS];
    int l0 = chunk * CLEN;
    for (int idx = threadIdx.x; idx < CLEN * DS; idx += blockDim.x) {
        int l = idx >> 4, n = idx & 15;
        sB[l][n] = g_xdbl[(size_t)(l0 + l) * XDBL + DTR + n];
        sC[l][n] = g_xdbl[(size_t)(l0 + l) * XDBL + DTR + DS + n];
    }
    __syncthreads();

    float Arow[DS], h[DS];
    bool chain = true;
    size_t base = ((size_t)chunk * DI + d) * DS;
    #pragma unroll
    for (int n = 0; n < DS; n++) {
        Arow[n] = -__expf(A_log[(size_t)d * DS + n]);
        h[n] = g_Hinit[base + n];
    }
    float r0 = Arow[0];
    #pragma unroll
    for (int n = 1; n < DS; n++)
        chain = chain && (fabsf(Arow[n] - (float)(n + 1) * r0)
                          <= 1e-5f * fabsf(Arow[n]) + 1e-7f);
    float Dd = Dp[d];

    for (int l = 0; l < CLEN; l++) {
        float dl = g_delta[(size_t)(l0 + l) * DI + d];
        float u  = g_xr[(size_t)(l0 + l) * DI + d];
        float du = dl * u;
        float y = 0.f;
        if (chain) {
            float q = __expf(dl * r0);
            float a = 1.f;
            #pragma unroll
            for (int n = 0; n < DS; n++) {
                a *= q;
                h[n] = fmaf(a, h[n], du * sB[l][n]);
                y = fmaf(h[n], sC[l][n], y);
            }
        } else {
            #pragma unroll
            for (int n = 0; n < DS; n++) {
                float a = __expf(dl * Arow[n]);
                h[n] = fmaf(a, h[n], du * sB[l][n]);
                y = fmaf(h[n], sC[l][n], y);
            }
        }
        y = fmaf(u, Dd, y);
        float res = g_xz[(size_t)(l0 + l) * DXZ + DI + d];
        float sig = 1.f / (1.f + __expf(-res));
        g_ya[(size_t)(l0 + l) * DI + d] = __float2half(y * (res * sig));
    }
}

// ---------------- launcher ----------------
extern "C" void kernel_launch(void* const* d_in, const int* in_sizes, int n_in,
                              void* d_out, int out_size) {
    const int*   ids        = (const int*)  d_in[0];
    const float* emb        = (const float*)d_in[1];
    const float* norm_w     = (const float*)d_in[2];
    const float* in_proj_w  = (const float*)d_in[3];
    const float* conv_w     = (const float*)d_in[4];
    const float* conv_b     = (const float*)d_in[5];
    const float* x_proj_w   = (const float*)d_in[6];
    const float* dt_proj_w  = (const float*)d_in[7];
    const float* dt_proj_b  = (const float*)d_in[8];
    const float* A_log      = (const float*)d_in[9];
    const float* Dp         = (const float*)d_in[10];
    const float* out_proj_w = (const float*)d_in[11];
    float* out = (float*)d_out;

    cudaFuncSetAttribute(gemm_fp16_kernel<0>,
                         cudaFuncAttributeMaxDynamicSharedMemorySize, SMEM_MMA);
    cudaFuncSetAttribute(gemm_fp16_kernel<1>,
                         cudaFuncAttributeMaxDynamicSharedMemorySize, SMEM_MMA);

    // resolve device-global scratch pointers
    __half *xn, *xrh, *ya, *dt, *wt, *wxp, *wdt;
    float *xz, *x_res, *part, *delta;
    cudaGetSymbolAddress((void**)&xn,    g_xn);
    cudaGetSymbolAddress((void**)&xrh,   g_xrh);
    cudaGetSymbolAddress((void**)&ya,    g_ya);
    cudaGetSymbolAddress((void**)&dt,    g_dt);
    cudaGetSymbolAddress((void**)&wt,    g_wt);
    cudaGetSymbolAddress((void**)&wxp,   g_wxp);
    cudaGetSymbolAddress((void**)&wdt,   g_wdt);
    cudaGetSymbolAddress((void**)&xz,    g_xz);
    cudaGetSymbolAddress((void**)&x_res, g_x);
    cudaGetSymbolAddress((void**)&part,  g_part);
    cudaGetSymbolAddress((void**)&delta, g_delta);

    embed_kernel<<<(LSEQ * DM + 255) / 256, 256>>>(ids, emb);

    for (int layer = 0; layer < NLAYER; layer++) {
        rmsnorm_kernel<<<LSEQ, 256>>>(norm_w + (size_t)layer * DM);

        // in_proj: [2048,768] @ [768,3072]
        wconv_kernel<<<dim3(DM / 32, DXZ / 32), dim3(32, 8)>>>(
            in_proj_w + (size_t)layer * DM * DXZ, wt, DM, DM, DXZ, DXZ);
        gemm_fp16_kernel<0><<<dim3(DXZ / 128, LSEQ / 128, 1), 256, SMEM_MMA>>>(
            xn, wt, xz, nullptr, DM, DM, DXZ, DXZ);

        // dt_proj weights convert early (independent)
        wconv_kernel<<<dim3(64 / 32, DI / 32), dim3(32, 8)>>>(
            dt_proj_w + (size_t)layer * DTR * DI, wdt, DTR, 64, DI, DI);

        conv_silu_kernel<<<(LSEQ * DI + 255) / 256, 256>>>(
            conv_w + (size_t)layer * DI * DCONV,
            conv_b + (size_t)layer * DI);

        // x_proj: [2048,1536] @ [1536,80] via split-K 8 + reduce
        wconv_kernel<<<dim3(DI / 32, 128 / 32), dim3(32, 8)>>>(
            x_proj_w + (size_t)layer * DI * XDBL, wxp, DI, DI, XDBL, 128);
        gemm_fp16_kernel<0><<<dim3(1, LSEQ / 128, 8), 256, SMEM_MMA>>>(
            xrh, wxp, part, nullptr, DI, DI / 8, XDBL, XDBL);
        xproj_reduce_kernel<<<(LSEQ * XDBL + 255) / 256, 256>>>();

        // dt_proj: [2048,64pad] @ [64pad,1536], softplus+bias epilogue
        gemm_fp16_kernel<1><<<dim3(DI / 128, LSEQ / 128, 1), 256, SMEM_MMA>>>(
            dt, wdt, delta, dt_proj_b + (size_t)layer * DI, 64, 64, DI, DI);

        scan_phaseA_kernel<<<dim3(DI / 128, NCH), 128>>>(
            A_log + (size_t)layer * DI * DS);
        scan_phaseB_kernel<<<(DI * DS + 255) / 256, 256>>>();
        scan_phaseC_kernel<<<dim3(DI / 128, NCH), 128>>>(
            A_log + (size_t)layer * DI * DS,
            Dp + (size_t)layer * DI);

        // out_proj: [2048,1536] @ [1536,768] via split-K 3 + residual reduce
        wconv_kernel<<<dim3(DI / 32, DM / 32), dim3(32, 8)>>>(
            out_proj_w + (size_t)layer * DI * DM, wt, DI, DI, DM, DM);
        gemm_fp16_kernel<0><<<dim3(DM / 128, LSEQ / 128, 3), 256, SMEM_MMA>>>(
            ya, wt, part, nullptr, DI, DI / 3, DM, DM);
        float* dest = (layer == NLAYER - 1) ? out : x_res;
        outproj_reduce_kernel<<<(LSEQ * DM + 255) / 256, 256>>>(dest);
    }
}

// round 7
// speedup vs baseline: 4.3985x; 1.3170x over previous
#include <cuda_runtime.h>
#include <cuda_fp16.h>
#include <math.h>
#include <stdint.h>

// ---------------- problem constants ----------------
#define LSEQ   2048
#define DM     768
#define DI     1536          // 2*DM
#define DXZ    3072          // 2*DI
#define DTR    48
#define DS     16
#define DCONV  4
#define NLAYER 2
#define XDBL   80            // DTR + 2*DS
#define NCH    64
#define CLEN   32            // LSEQ / NCH

// ---------------- scratch (device globals, no allocation) ----------------
__device__ __align__(16) float g_x   [LSEQ * DM];    // residual stream
__device__ __align__(16) float g_xz  [LSEQ * DXZ];   // in_proj output (xr | res)
__device__ __align__(16) float g_xr  [LSEQ * DI];    // conv+silu output (fp32 for scan)
__device__ __align__(16) float g_xdbl[LSEQ * XDBL];  // x_proj output (dt | B | C)
__device__ __align__(16) float g_delta[LSEQ * DI];   // softplus(dt@dt_proj + b)
__device__ __align__(16) float g_Aprod[NCH * DI * DS];
__device__ __align__(16) float g_Hend [NCH * DI * DS];
__device__ __align__(16) float g_Hinit[NCH * DI * DS];

// fp16 activations for tensor-core GEMMs
__device__ __align__(16) __half g_xn [LSEQ * DM];
__device__ __align__(16) __half g_xrh[LSEQ * DI];
__device__ __align__(16) __half g_ya [LSEQ * DI];
__device__ __align__(16) __half g_dt [LSEQ * 64];     // dt cols padded 48->64
// fp16 weights, transposed [N][K]
__device__ __align__(16) __half g_wt [DM * DXZ];      // in_proj / out_proj
__device__ __align__(16) __half g_wxp[128 * DI];      // x_proj [80->128 pad][1536]
__device__ __align__(16) __half g_wdt[DI * 64];       // dt_proj [1536][48->64 pad]
// split-K partials
__device__ __align__(16) float g_part[3 * LSEQ * DM];

// ---------------- small helpers ----------------
__device__ __forceinline__ uint32_t smem_u32(const void* p) {
    uint32_t a;
    asm("{ .reg .u64 t; cvta.to.shared.u64 t, %1; cvt.u32.u64 %0, t; }"
        : "=r"(a) : "l"(p));
    return a;
}
__device__ __forceinline__ void ldm4(uint32_t addr, uint32_t r[4]) {
    asm volatile("ldmatrix.sync.aligned.m8n8.x4.shared.b16 {%0,%1,%2,%3}, [%4];"
                 : "=r"(r[0]), "=r"(r[1]), "=r"(r[2]), "=r"(r[3]) : "r"(addr));
}
__device__ __forceinline__ void mma16816(float c[4], const uint32_t a[4],
                                         const uint32_t b0, const uint32_t b1) {
    asm volatile(
        "mma.sync.aligned.m16n8k16.row.col.f32.f16.f16.f32 "
        "{%0,%1,%2,%3}, {%4,%5,%6,%7}, {%8,%9}, {%0,%1,%2,%3};"
        : "+f"(c[0]), "+f"(c[1]), "+f"(c[2]), "+f"(c[3])
        : "r"(a[0]), "r"(a[1]), "r"(a[2]), "r"(a[3]), "r"(b0), "r"(b1));
}

// ---------------- single-term fp16 GEMM via mma.sync ----------------
// C[2048,N] = A[2048,K] @ B^T with B as [N][K] row-major fp16.
// Tile 128x128, K-slab 32, 3 stages x 2 tiles, 2 CTAs/SM (128-reg budget),
// fragment-first mainloop, 1 sync/slab.
#define SROW    40                       // 32 halfs + 8 pad
#define TILE_E  (128 * SROW)             // 5120 halfs = 10240 B
#define NSTAGE  3
#define SMEM_MMA (NSTAGE * 2 * TILE_E * 2)   // 61440 B

__device__ __forceinline__ void mma_load_stage(
        uint32_t smb, int stage,
        const __half* __restrict__ A, const __half* __restrict__ B,
        int row0, int col0, int k0, int K, int tid) {
    #pragma unroll
    for (int t = 0; t < 2; t++) {
        const __half* src = (t == 0) ? A : B;
        int r0 = (t == 0) ? row0 : col0;
        #pragma unroll
        for (int i = 0; i < 2; i++) {
            int c = tid + i * 256;
            int row = c >> 2, kc = (c & 3) * 8;
            uint32_t dst = smb + (uint32_t)(((stage * 2 + t) * TILE_E) + row * SROW + kc) * 2u;
            const void* gsrc = src + (size_t)(r0 + row) * K + k0 + kc;
            asm volatile("cp.async.cg.shared.global [%0], [%1], 16;"
                         :: "r"(dst), "l"(gsrc));
        }
    }
    asm volatile("cp.async.commit_group;" ::: "memory");
}

// MODE 0: plain write   MODE 1: softplus(v + bias[n])
template<int MODE>
__global__ void __launch_bounds__(256, 2)
gemm_fp16_kernel(const __half* __restrict__ Ag, const __half* __restrict__ Bg,
                 float* __restrict__ C, const float* __restrict__ bias,
                 int K, int ksize, int ldc, int Nvalid) {
    extern __shared__ __half sm[];
    const int tid = threadIdx.x, lane = tid & 31, wid = tid >> 5;
    const int wm = wid & 3, wn = wid >> 2;         // 4 m-warps x 2 n-warps
    const int row0 = blockIdx.y * 128, col0 = blockIdx.x * 128;
    const int kb = blockIdx.z * ksize;
    C += (size_t)blockIdx.z * LSEQ * ldc;
    uint32_t smb = smem_u32(sm);

    float acc[2][8][4] = {};
    const int S = ksize / 32;

    mma_load_stage(smb, 0, Ag, Bg, row0, col0, kb, K, tid);
    mma_load_stage(smb, 1, Ag, Bg, row0, col0, kb + 32, K, tid);

    const int lrow = lane & 15, lcol = (lane >> 4) * 8;

    for (int s = 0; s < S; s++) {
        if (s + 1 < S) {
            asm volatile("cp.async.wait_group 1;" ::: "memory");
        } else {
            asm volatile("cp.async.wait_group 0;" ::: "memory");
        }
        __syncthreads();
        if (s + 2 < S)
            mma_load_stage(smb, (s + 2) % NSTAGE, Ag, Bg,
                           row0, col0, kb + (s + 2) * 32, K, tid);

        int st = s % NSTAGE;
        uint32_t bA = smb + (uint32_t)((st * 2 + 0) * TILE_E) * 2u;
        uint32_t bB = smb + (uint32_t)((st * 2 + 1) * TILE_E) * 2u;

        // fragment-first: load ALL slab fragments, then issue all MMAs (ILP)
        uint32_t ah[2][2][4];   // [kk2][mt]
        uint32_t bb[2][4][4];   // [kk2][g]
        #pragma unroll
        for (int kk2 = 0; kk2 < 2; kk2++) {
            int kk = kk2 * 16;
            #pragma unroll
            for (int mt = 0; mt < 2; mt++) {
                uint32_t off = (uint32_t)((wm * 32 + mt * 16 + lrow) * SROW + kk + lcol) * 2u;
                ldm4(bA + off, ah[kk2][mt]);
            }
            #pragma unroll
            for (int g = 0; g < 4; g++) {
                uint32_t off = (uint32_t)((wn * 64 + g * 16 + lrow) * SROW + kk + lcol) * 2u;
                ldm4(bB + off, bb[kk2][g]);
            }
        }
        #pragma unroll
        for (int kk2 = 0; kk2 < 2; kk2++) {
            #pragma unroll
            for (int g = 0; g < 4; g++) {
                #pragma unroll
                for (int mt = 0; mt < 2; mt++) {
                    mma16816(acc[mt][2 * g + 0], ah[kk2][mt], bb[kk2][g][0], bb[kk2][g][2]);
                    mma16816(acc[mt][2 * g + 1], ah[kk2][mt], bb[kk2][g][1], bb[kk2][g][3]);
                }
            }
        }
    }

    // epilogue
    int gq = lane >> 2, tq = lane & 3;
    #pragma unroll
    for (int mt = 0; mt < 2; mt++) {
        #pragma unroll
        for (int n8 = 0; n8 < 8; n8++) {
            int rm = row0 + wm * 32 + mt * 16 + gq;
            int cn = col0 + wn * 64 + n8 * 8 + 2 * tq;
            if (cn >= Nvalid) continue;
            float v[4] = {acc[mt][n8][0], acc[mt][n8][1],
                          acc[mt][n8][2], acc[mt][n8][3]};
            if (MODE == 1) {
                float b0 = bias[cn], b1 = bias[cn + 1];
                v[0] += b0; v[1] += b1; v[2] += b0; v[3] += b1;
                #pragma unroll
                for (int q = 0; q < 4; q++)
                    v[q] = (v[q] > 20.f) ? v[q] : log1pf(__expf(v[q]));
            }
            *reinterpret_cast<float2*>(C + (size_t)rm * ldc + cn) =
                make_float2(v[0], v[1]);
            *reinterpret_cast<float2*>(C + (size_t)(rm + 8) * ldc + cn) =
                make_float2(v[2], v[3]);
        }
    }
}

// reduce 8 x_proj split-K partials -> g_xdbl, emit fp16 dt cols (pad 64)
__global__ void xproj_reduce_kernel() {
    int i = blockIdx.x * blockDim.x + threadIdx.x;
    if (i >= LSEQ * XDBL) return;
    float s = 0.f;
    #pragma unroll
    for (int z = 0; z < 8; z++) s += g_part[(size_t)z * LSEQ * XDBL + i];
    g_xdbl[i] = s;
    int l = i / XDBL, c = i - l * XDBL;
    if (c < 64) g_dt[(size_t)l * 64 + c] = __float2half(s);
}

// reduce 3 out_proj split-K partials + residual -> dest
__global__ void outproj_reduce_kernel(float* __restrict__ dest) {
    int i = blockIdx.x * blockDim.x + threadIdx.x;
    if (i >= LSEQ * DM) return;
    float s = g_x[i];
    #pragma unroll
    for (int z = 0; z < 3; z++) s += g_part[(size_t)z * LSEQ * DM + i];
    dest[i] = s;
}

// ---------------- elementwise kernels ----------------
__global__ void embed_kernel(const int* __restrict__ ids,
                             const float* __restrict__ emb) {
    int i = blockIdx.x * blockDim.x + threadIdx.x;
    if (i >= LSEQ * DM) return;
    int l = i / DM, d = i - l * DM;
    g_x[i] = emb[(size_t)ids[l] * DM + d];
}

// rmsnorm fused with fp16 output
__global__ void rmsnorm_kernel(const float* __restrict__ w) {
    int l = blockIdx.x;
    const float* xr = &g_x[(size_t)l * DM];
    float s = 0.f;
    for (int d = threadIdx.x; d < DM; d += 256) {
        float v = xr[d];
        s += v * v;
    }
    __shared__ float red[8];
    #pragma unroll
    for (int o = 16; o; o >>= 1) s += __shfl_xor_sync(0xffffffffu, s, o);
    if ((threadIdx.x & 31) == 0) red[threadIdx.x >> 5] = s;
    __syncthreads();
    if (threadIdx.x < 8) {
        float t = red[threadIdx.x];
        #pragma unroll
        for (int o = 4; o; o >>= 1) t += __shfl_xor_sync(0xffu, t, o);
        if (threadIdx.x == 0) red[0] = rsqrtf(t / (float)DM + 1e-5f);
    }
    __syncthreads();
    float rinv = red[0];
    for (int d = threadIdx.x; d < DM; d += 256)
        g_xn[(size_t)l * DM + d] = __float2half(xr[d] * rinv * w[d]);
}

// transpose weights: W fp32 [Kin][N] -> fp16 [n][k] for n<Npad, k<Kpad
__global__ void wconv_kernel(const float* __restrict__ W, __half* __restrict__ out,
                             int Kin, int Kpad, int N, int Npad) {
    __shared__ float t[32][33];
    int k0 = blockIdx.x * 32, n0 = blockIdx.y * 32;
    #pragma unroll
    for (int i = 0; i < 4; i++) {
        int k = k0 + threadIdx.y + i * 8;
        int n = n0 + threadIdx.x;
        t[threadIdx.y + i * 8][threadIdx.x] =
            (k < Kin && n < N) ? W[(size_t)k * N + n] : 0.f;
    }
    __syncthreads();
    #pragma unroll
    for (int i = 0; i < 4; i++) {
        int n = n0 + threadIdx.y + i * 8;
        int k = k0 + threadIdx.x;
        if (n < Npad && k < Kpad)
            out[(size_t)n * Kpad + k] = __float2half(t[threadIdx.x][threadIdx.y + i * 8]);
    }
}

// conv + silu, emits fp32 (for scan) and fp16 (for x_proj GEMM)
__global__ void conv_silu_kernel(const float* __restrict__ w,
                                 const float* __restrict__ b) {
    int i = blockIdx.x * blockDim.x + threadIdx.x;
    if (i >= LSEQ * DI) return;
    int l = i / DI, d = i - l * DI;
    float s = b[d];
    #pragma unroll
    for (int k = 0; k < DCONV; k++) {
        int ll = l - (DCONV - 1) + k;
        if (ll >= 0) s = fmaf(w[d * DCONV + k], g_xz[(size_t)ll * DXZ + d], s);
    }
    float sig = 1.f / (1.f + __expf(-s));
    float v = s * sig;
    g_xr[i] = v;
    g_xrh[i] = __float2half(v);
}

// ---------------- chunked selective scan (power-chain exp) ----------------
__global__ void scan_phaseA_kernel(const float* __restrict__ A_log) {
    int d = blockIdx.x * blockDim.x + threadIdx.x;
    int chunk = blockIdx.y;
    __shared__ float sB[CLEN][DS];
    int l0 = chunk * CLEN;
    for (int idx = threadIdx.x; idx < CLEN * DS; idx += blockDim.x) {
        int l = idx >> 4, n = idx & 15;
        sB[l][n] = g_xdbl[(size_t)(l0 + l) * XDBL + DTR + n];
    }
    __syncthreads();

    float Arow[DS], h[DS], P[DS];
    bool chain = true;
    #pragma unroll
    for (int n = 0; n < DS; n++) {
        Arow[n] = -__expf(A_log[(size_t)d * DS + n]);
        h[n] = 0.f; P[n] = 1.f;
    }
    float r0 = Arow[0];
    #pragma unroll
    for (int n = 1; n < DS; n++)
        chain = chain && (fabsf(Arow[n] - (float)(n + 1) * r0)
                          <= 1e-5f * fabsf(Arow[n]) + 1e-7f);

    if (chain) {
        for (int l = 0; l < CLEN; l++) {
            float dl = g_delta[(size_t)(l0 + l) * DI + d];
            float du = dl * g_xr[(size_t)(l0 + l) * DI + d];
            float q = __expf(dl * r0);
            float a = 1.f;
            #pragma unroll
            for (int n = 0; n < DS; n++) {
                a *= q;
                h[n] = fmaf(a, h[n], du * sB[l][n]);
                P[n] *= a;
            }
        }
    } else {
        for (int l = 0; l < CLEN; l++) {
            float dl = g_delta[(size_t)(l0 + l) * DI + d];
            float du = dl * g_xr[(size_t)(l0 + l) * DI + d];
            #pragma unroll
            for (int n = 0; n < DS; n++) {
                float a = __expf(dl * Arow[n]);
                h[n] = fmaf(a, h[n], du * sB[l][n]);
                P[n] *= a;
            }
        }
    }
    size_t base = ((size_t)chunk * DI + d) * DS;
    #pragma unroll
    for (int n = 0; n < DS; n++) {
        g_Aprod[base + n] = P[n];
        g_Hend [base + n] = h[n];
    }
}

__global__ void scan_phaseB_kernel() {
    int i = blockIdx.x * blockDim.x + threadIdx.x;
    if (i >= DI * DS) return;
    float run = 0.f;
    #pragma unroll 8
    for (int c = 0; c < NCH; c++) {
        size_t idx = (size_t)c * DI * DS + i;
        g_Hinit[idx] = run;
        run = fmaf(g_Aprod[idx], run, g_Hend[idx]);
    }
}

__global__ void scan_phaseC_kernel(const float* __restrict__ A_log,
                                   const float* __restrict__ Dp) {
    int d = blockIdx.x * blockDim.x + threadIdx.x;
    int chunk = blockIdx.y;
    __shared__ float sB[CLEN][DS];
    __shared__ float sC[CLEN][DS];
    int l0 = chunk * CLEN;
    for (int idx = threadIdx.x; idx < CLEN * DS; idx += blockDim.x) {
        int l = idx >> 4, n = idx & 15;
        sB[l][n] = g_xdbl[(size_t)(l0 + l) * XDBL + DTR + n];
        sC[l][n] = g_xdbl[(size_t)(l0 + l) * XDBL + DTR + DS + n];
    }
    __syncthreads();

    float Arow[DS], h[DS];
    bool chain = true;
    size_t base = ((size_t)chunk * DI + d) * DS;
    #pragma unroll
    for (int n = 0; n < DS; n++) {
        Arow[n] = -__expf(A_log[(size_t)d * DS + n]);
        h[n] = g_Hinit[base + n];
    }
    float r0 = Arow[0];
    #pragma unroll
    for (int n = 1; n < DS; n++)
        chain = chain && (fabsf(Arow[n] - (float)(n + 1) * r0)
                          <= 1e-5f * fabsf(Arow[n]) + 1e-7f);
    float Dd = Dp[d];

    for (int l = 0; l < CLEN; l++) {
        float dl = g_delta[(size_t)(l0 + l) * DI + d];
        float u  = g_xr[(size_t)(l0 + l) * DI + d];
        float du = dl * u;
        float y = 0.f;
        if (chain) {
            float q = __expf(dl * r0);
            float a = 1.f;
            #pragma unroll
            for (int n = 0; n < DS; n++) {
                a *= q;
                h[n] = fmaf(a, h[n], du * sB[l][n]);
                y = fmaf(h[n], sC[l][n], y);
            }
        } else {
            #pragma unroll
            for (int n = 0; n < DS; n++) {
                float a = __expf(dl * Arow[n]);
                h[n] = fmaf(a, h[n], du * sB[l][n]);
                y = fmaf(h[n], sC[l][n], y);
            }
        }
        y = fmaf(u, Dd, y);
        float res = g_xz[(size_t)(l0 + l) * DXZ + DI + d];
        float sig = 1.f / (1.f + __expf(-res));
        g_ya[(size_t)(l0 + l) * DI + d] = __float2half(y * (res * sig));
    }
}

// ---------------- launcher ----------------
extern "C" void kernel_launch(void* const* d_in, const int* in_sizes, int n_in,
                              void* d_out, int out_size) {
    const int*   ids        = (const int*)  d_in[0];
    const float* emb        = (const float*)d_in[1];
    const float* norm_w     = (const float*)d_in[2];
    const float* in_proj_w  = (const float*)d_in[3];
    const float* conv_w     = (const float*)d_in[4];
    const float* conv_b     = (const float*)d_in[5];
    const float* x_proj_w   = (const float*)d_in[6];
    const float* dt_proj_w  = (const float*)d_in[7];
    const float* dt_proj_b  = (const float*)d_in[8];
    const float* A_log      = (const float*)d_in[9];
    const float* Dp         = (const float*)d_in[10];
    const float* out_proj_w = (const float*)d_in[11];
    float* out = (float*)d_out;

    cudaFuncSetAttribute(gemm_fp16_kernel<0>,
                         cudaFuncAttributeMaxDynamicSharedMemorySize, SMEM_MMA);
    cudaFuncSetAttribute(gemm_fp16_kernel<1>,
                         cudaFuncAttributeMaxDynamicSharedMemorySize, SMEM_MMA);

    // resolve device-global scratch pointers
    __half *xn, *xrh, *ya, *dt, *wt, *wxp, *wdt;
    float *xz, *x_res, *part, *delta;
    cudaGetSymbolAddress((void**)&xn,    g_xn);
    cudaGetSymbolAddress((void**)&xrh,   g_xrh);
    cudaGetSymbolAddress((void**)&ya,    g_ya);
    cudaGetSymbolAddress((void**)&dt,    g_dt);
    cudaGetSymbolAddress((void**)&wt,    g_wt);
    cudaGetSymbolAddress((void**)&wxp,   g_wxp);
    cudaGetSymbolAddress((void**)&wdt,   g_wdt);
    cudaGetSymbolAddress((void**)&xz,    g_xz);
    cudaGetSymbolAddress((void**)&x_res, g_x);
    cudaGetSymbolAddress((void**)&part,  g_part);
    cudaGetSymbolAddress((void**)&delta, g_delta);

    embed_kernel<<<(LSEQ * DM + 255) / 256, 256>>>(ids, emb);

    for (int layer = 0; layer < NLAYER; layer++) {
        rmsnorm_kernel<<<LSEQ, 256>>>(norm_w + (size_t)layer * DM);

        // in_proj: [2048,768] @ [768,3072]
        wconv_kernel<<<dim3(DM / 32, DXZ / 32), dim3(32, 8)>>>(
            in_proj_w + (size_t)layer * DM * DXZ, wt, DM, DM, DXZ, DXZ);
        gemm_fp16_kernel<0><<<dim3(DXZ / 128, LSEQ / 128, 1), 256, SMEM_MMA>>>(
            xn, wt, xz, nullptr, DM, DM, DXZ, DXZ);

        // dt_proj weights convert early (independent)
        wconv_kernel<<<dim3(64 / 32, DI / 32), dim3(32, 8)>>>(
            dt_proj_w + (size_t)layer * DTR * DI, wdt, DTR, 64, DI, DI);

        conv_silu_kernel<<<(LSEQ * DI + 255) / 256, 256>>>(
            conv_w + (size_t)layer * DI * DCONV,
            conv_b + (size_t)layer * DI);

        // x_proj: [2048,1536] @ [1536,80] via split-K 8 + reduce
        wconv_kernel<<<dim3(DI / 32, 128 / 32), dim3(32, 8)>>>(
            x_proj_w + (size_t)layer * DI * XDBL, wxp, DI, DI, XDBL, 128);
        gemm_fp16_kernel<0><<<dim3(1, LSEQ / 128, 8), 256, SMEM_MMA>>>(
            xrh, wxp, part, nullptr, DI, DI / 8, XDBL, XDBL);
        xproj_reduce_kernel<<<(LSEQ * XDBL + 255) / 256, 256>>>();

        // dt_proj: [2048,64pad] @ [64pad,1536], softplus+bias epilogue
        gemm_fp16_kernel<1><<<dim3(DI / 128, LSEQ / 128, 1), 256, SMEM_MMA>>>(
            dt, wdt, delta, dt_proj_b + (size_t)layer * DI, 64, 64, DI, DI);

        scan_phaseA_kernel<<<dim3(DI / 128, NCH), 128>>>(
            A_log + (size_t)layer * DI * DS);
        scan_phaseB_kernel<<<(DI * DS + 255) / 256, 256>>>();
        scan_phaseC_kernel<<<dim3(DI / 128, NCH), 128>>>(
            A_log + (size_t)layer * DI * DS,
            Dp + (size_t)layer * DI);

        // out_proj: [2048,1536] @ [1536,768] via split-K 3 + residual reduce
        wconv_kernel<<<dim3(DI / 32, DM / 32), dim3(32, 8)>>>(
            out_proj_w + (size_t)layer * DI * DM, wt, DI, DI, DM, DM);
        gemm_fp16_kernel<0><<<dim3(DM / 128, LSEQ / 128, 3), 256, SMEM_MMA>>>(
            ya, wt, part, nullptr, DI, DI / 3, DM, DM);
        float* dest = (layer == NLAYER - 1) ? out : x_res;
        outproj_reduce_kernel<<<(LSEQ * DM + 255) / 256, 256>>>(dest);
    }
}

// round 8
// speedup vs baseline: 4.7939x; 1.0899x over previous
#include <cuda_runtime.h>
#include <cuda_fp16.h>
#include <math.h>
#include <stdint.h>

// ---------------- problem constants ----------------
#define LSEQ   2048
#define DM     768
#define DI     1536          // 2*DM
#define DXZ    3072          // 2*DI
#define DTR    48
#define DS     16
#define DCONV  4
#define NLAYER 2
#define XDBL   80            // DTR + 2*DS
#define NCH    64
#define CLEN   32            // LSEQ / NCH

// ---------------- scratch (device globals, no allocation) ----------------
__device__ __align__(16) float g_x   [LSEQ * DM];    // residual stream
__device__ __align__(16) float g_xz  [LSEQ * DXZ];   // in_proj output (xr | res)
__device__ __align__(16) float g_xr  [LSEQ * DI];    // conv+silu output (fp32 for scan)
__device__ __align__(16) float g_xdbl[LSEQ * XDBL];  // x_proj output (dt | B | C)
__device__ __align__(16) float g_delta[LSEQ * DI];   // softplus(dt@dt_proj + b)
__device__ __align__(16) float g_Aprod[NCH * DI * DS];
__device__ __align__(16) float g_Hend [NCH * DI * DS];
__device__ __align__(16) float g_Hinit[NCH * DI * DS];

// fp16 activations for tensor-core GEMMs
__device__ __align__(16) __half g_xn [LSEQ * DM];
__device__ __align__(16) __half g_xrh[LSEQ * DI];
__device__ __align__(16) __half g_ya [LSEQ * DI];
__device__ __align__(16) __half g_dt [LSEQ * 64];     // dt cols padded 48->64
// fp16 weights, transposed [N][K]
__device__ __align__(16) __half g_wt [DM * DXZ];      // in_proj / out_proj (per-layer reuse)
__device__ __align__(16) __half g_wxp[128 * DI];      // x_proj [80->128 pad][1536]
__device__ __align__(16) __half g_wdt[DI * 64];       // dt_proj [1536][48->64 pad]
// split-K partials
__device__ __align__(16) float g_part[3 * LSEQ * DM];

// ---------------- small helpers ----------------
__device__ __forceinline__ uint32_t smem_u32(const void* p) {
    uint32_t a;
    asm("{ .reg .u64 t; cvta.to.shared.u64 t, %1; cvt.u32.u64 %0, t; }"
        : "=r"(a) : "l"(p));
    return a;
}
__device__ __forceinline__ void ldm4(uint32_t addr, uint32_t r[4]) {
    asm volatile("ldmatrix.sync.aligned.m8n8.x4.shared.b16 {%0,%1,%2,%3}, [%4];"
                 : "=r"(r[0]), "=r"(r[1]), "=r"(r[2]), "=r"(r[3]) : "r"(addr));
}
__device__ __forceinline__ void mma16816(float c[4], const uint32_t a[4],
                                         const uint32_t b0, const uint32_t b1) {
    asm volatile(
        "mma.sync.aligned.m16n8k16.row.col.f32.f16.f16.f32 "
        "{%0,%1,%2,%3}, {%4,%5,%6,%7}, {%8,%9}, {%0,%1,%2,%3};"
        : "+f"(c[0]), "+f"(c[1]), "+f"(c[2]), "+f"(c[3])
        : "r"(a[0]), "r"(a[1]), "r"(a[2]), "r"(a[3]), "r"(b0), "r"(b1));
}

// ---------------- single-term fp16 GEMM via mma.sync ----------------
// C[2048,N] = A[2048,K] @ B^T with B as [N][K] row-major fp16.
// Tile 128x128, K-slab 64, 3 stages x 2 tiles (110.6KB), 2 CTAs/SM,
// fragment-first mainloop per 32-half, 1 sync per 64-K slab.
#define SROW    72                       // 64 halfs + 8 pad (144B row stride)
#define TILE_E  (128 * SROW)             // 9216 halfs = 18432 B
#define NSTAGE  3
#define SMEM_MMA (NSTAGE * 2 * TILE_E * 2)   // 110592 B

__device__ __forceinline__ void mma_load_stage(
        uint32_t smb, int stage,
        const __half* __restrict__ A, const __half* __restrict__ B,
        int row0, int col0, int k0, int K, int tid) {
    #pragma unroll
    for (int t = 0; t < 2; t++) {
        const __half* src = (t == 0) ? A : B;
        int r0 = (t == 0) ? row0 : col0;
        #pragma unroll
        for (int i = 0; i < 4; i++) {
            int c = tid + i * 256;
            int row = c >> 3, kc = (c & 7) * 8;
            uint32_t dst = smb + (uint32_t)(((stage * 2 + t) * TILE_E) + row * SROW + kc) * 2u;
            const void* gsrc = src + (size_t)(r0 + row) * K + k0 + kc;
            asm volatile("cp.async.cg.shared.global [%0], [%1], 16;"
                         :: "r"(dst), "l"(gsrc));
        }
    }
    asm volatile("cp.async.commit_group;" ::: "memory");
}

// MODE 0: plain write   MODE 1: softplus(v + bias[n])
template<int MODE>
__global__ void __launch_bounds__(256, 2)
gemm_fp16_kernel(const __half* __restrict__ Ag, const __half* __restrict__ Bg,
                 float* __restrict__ C, const float* __restrict__ bias,
                 int K, int ksize, int ldc, int Nvalid) {
    extern __shared__ __half sm[];
    const int tid = threadIdx.x, lane = tid & 31, wid = tid >> 5;
    const int wm = wid & 3, wn = wid >> 2;         // 4 m-warps x 2 n-warps
    const int row0 = blockIdx.y * 128, col0 = blockIdx.x * 128;
    const int kb = blockIdx.z * ksize;
    C += (size_t)blockIdx.z * LSEQ * ldc;
    uint32_t smb = smem_u32(sm);

    float acc[2][8][4] = {};
    const int S = ksize / 64;

    mma_load_stage(smb, 0, Ag, Bg, row0, col0, kb, K, tid);
    if (S > 1) mma_load_stage(smb, 1, Ag, Bg, row0, col0, kb + 64, K, tid);

    const int lrow = lane & 15, lcol0 = (lane >> 4) * 8;

    for (int s = 0; s < S; s++) {
        if (s + 1 < S) {
            asm volatile("cp.async.wait_group 1;" ::: "memory");
        } else {
            asm volatile("cp.async.wait_group 0;" ::: "memory");
        }
        __syncthreads();
        if (s + 2 < S)
            mma_load_stage(smb, (s + 2) % NSTAGE, Ag, Bg,
                           row0, col0, kb + (s + 2) * 64, K, tid);

        int st = s % NSTAGE;
        uint32_t bA = smb + (uint32_t)((st * 2 + 0) * TILE_E) * 2u;
        uint32_t bB = smb + (uint32_t)((st * 2 + 1) * TILE_E) * 2u;

        #pragma unroll
        for (int kh = 0; kh < 64; kh += 32) {
            // fragment-first per 32-K half: 12 LDSM then 16 MMA
            uint32_t ah[2][2][4];   // [kk2][mt]
            uint32_t bb[2][4][4];   // [kk2][g]
            #pragma unroll
            for (int kk2 = 0; kk2 < 2; kk2++) {
                int kk = kh + kk2 * 16;
                #pragma unroll
                for (int mt = 0; mt < 2; mt++) {
                    uint32_t off = (uint32_t)((wm * 32 + mt * 16 + lrow) * SROW + kk + lcol0) * 2u;
                    ldm4(bA + off, ah[kk2][mt]);
                }
                #pragma unroll
                for (int g = 0; g < 4; g++) {
                    uint32_t off = (uint32_t)((wn * 64 + g * 16 + lrow) * SROW + kk + lcol0) * 2u;
                    ldm4(bB + off, bb[kk2][g]);
                }
            }
            #pragma unroll
            for (int kk2 = 0; kk2 < 2; kk2++) {
                #pragma unroll
                for (int g = 0; g < 4; g++) {
                    #pragma unroll
                    for (int mt = 0; mt < 2; mt++) {
                        mma16816(acc[mt][2 * g + 0], ah[kk2][mt], bb[kk2][g][0], bb[kk2][g][2]);
                        mma16816(acc[mt][2 * g + 1], ah[kk2][mt], bb[kk2][g][1], bb[kk2][g][3]);
                    }
                }
            }
        }
    }

    // epilogue
    int gq = lane >> 2, tq = lane & 3;
    #pragma unroll
    for (int mt = 0; mt < 2; mt++) {
        #pragma unroll
        for (int n8 = 0; n8 < 8; n8++) {
            int rm = row0 + wm * 32 + mt * 16 + gq;
            int cn = col0 + wn * 64 + n8 * 8 + 2 * tq;
            if (cn >= Nvalid) continue;
            float v[4] = {acc[mt][n8][0], acc[mt][n8][1],
                          acc[mt][n8][2], acc[mt][n8][3]};
            if (MODE == 1) {
                float b0 = bias[cn], b1 = bias[cn + 1];
                v[0] += b0; v[1] += b1; v[2] += b0; v[3] += b1;
                #pragma unroll
                for (int q = 0; q < 4; q++)
                    v[q] = (v[q] > 20.f) ? v[q] : log1pf(__expf(v[q]));
            }
            *reinterpret_cast<float2*>(C + (size_t)rm * ldc + cn) =
                make_float2(v[0], v[1]);
            *reinterpret_cast<float2*>(C + (size_t)(rm + 8) * ldc + cn) =
                make_float2(v[2], v[3]);
        }
    }
}

// reduce 8 x_proj split-K partials -> g_xdbl, emit fp16 dt cols (pad 64)
__global__ void xproj_reduce_kernel() {
    int i = blockIdx.x * blockDim.x + threadIdx.x;
    if (i >= LSEQ * XDBL) return;
    float s = 0.f;
    #pragma unroll
    for (int z = 0; z < 8; z++) s += g_part[(size_t)z * LSEQ * XDBL + i];
    g_xdbl[i] = s;
    int l = i / XDBL, c = i - l * XDBL;
    if (c < 64) g_dt[(size_t)l * 64 + c] = __float2half(s);
}

// ---------------- fused residual-reduce + rmsnorm ----------------
// dest = g_x + sum(part);  if norm_w: also write g_xn = rms(dest)*w
__global__ void outred_rms_kernel(const float* __restrict__ norm_w,
                                  float* __restrict__ dest, int do_norm) {
    int l = blockIdx.x;
    float v[3];
    float s = 0.f;
    #pragma unroll
    for (int i = 0; i < 3; i++) {
        int d = threadIdx.x + i * 256;
        size_t idx = (size_t)l * DM + d;
        float t = g_x[idx];
        #pragma unroll
        for (int z = 0; z < 3; z++) t += g_part[(size_t)z * LSEQ * DM + idx];
        dest[idx] = t;
        v[i] = t;
        s += t * t;
    }
    if (!do_norm) return;
    __shared__ float red[8];
    #pragma unroll
    for (int o = 16; o; o >>= 1) s += __shfl_xor_sync(0xffffffffu, s, o);
    if ((threadIdx.x & 31) == 0) red[threadIdx.x >> 5] = s;
    __syncthreads();
    if (threadIdx.x < 8) {
        float t = red[threadIdx.x];
        #pragma unroll
        for (int o = 4; o; o >>= 1) t += __shfl_xor_sync(0xffu, t, o);
        if (threadIdx.x == 0) red[0] = rsqrtf(t / (float)DM + 1e-5f);
    }
    __syncthreads();
    float rinv = red[0];
    #pragma unroll
    for (int i = 0; i < 3; i++) {
        int d = threadIdx.x + i * 256;
        g_xn[(size_t)l * DM + d] = __float2half(v[i] * rinv * norm_w[d]);
    }
}

// ---------------- fused embed + rmsnorm (layer 0 entry) ----------------
__global__ void embed_rms_kernel(const int* __restrict__ ids,
                                 const float* __restrict__ emb,
                                 const float* __restrict__ norm_w) {
    int l = blockIdx.x;
    const float* erow = emb + (size_t)ids[l] * DM;
    float v[3];
    float s = 0.f;
    #pragma unroll
    for (int i = 0; i < 3; i++) {
        int d = threadIdx.x + i * 256;
        float t = erow[d];
        g_x[(size_t)l * DM + d] = t;
        v[i] = t;
        s += t * t;
    }
    __shared__ float red[8];
    #pragma unroll
    for (int o = 16; o; o >>= 1) s += __shfl_xor_sync(0xffffffffu, s, o);
    if ((threadIdx.x & 31) == 0) red[threadIdx.x >> 5] = s;
    __syncthreads();
    if (threadIdx.x < 8) {
        float t = red[threadIdx.x];
        #pragma unroll
        for (int o = 4; o; o >>= 1) t += __shfl_xor_sync(0xffu, t, o);
        if (threadIdx.x == 0) red[0] = rsqrtf(t / (float)DM + 1e-5f);
    }
    __syncthreads();
    float rinv = red[0];
    #pragma unroll
    for (int i = 0; i < 3; i++) {
        int d = threadIdx.x + i * 256;
        g_xn[(size_t)l * DM + d] = __float2half(v[i] * rinv * norm_w[d]);
    }
}

// transpose weights: W fp32 [Kin][N] -> fp16 [n][k] for n<Npad, k<Kpad
__global__ void wconv_kernel(const float* __restrict__ W, __half* __restrict__ out,
                             int Kin, int Kpad, int N, int Npad) {
    __shared__ float t[32][33];
    int k0 = blockIdx.x * 32, n0 = blockIdx.y * 32;
    #pragma unroll
    for (int i = 0; i < 4; i++) {
        int k = k0 + threadIdx.y + i * 8;
        int n = n0 + threadIdx.x;
        t[threadIdx.y + i * 8][threadIdx.x] =
            (k < Kin && n < N) ? W[(size_t)k * N + n] : 0.f;
    }
    __syncthreads();
    #pragma unroll
    for (int i = 0; i < 4; i++) {
        int n = n0 + threadIdx.y + i * 8;
        int k = k0 + threadIdx.x;
        if (n < Npad && k < Kpad)
            out[(size_t)n * Kpad + k] = __float2half(t[threadIdx.x][threadIdx.y + i * 8]);
    }
}

// conv + silu: 8 outputs along l per thread, taps reused in registers
__global__ void conv_silu_kernel(const float* __restrict__ w,
                                 const float* __restrict__ b) {
    int d = blockIdx.x * 256 + threadIdx.x;          // gridDim.x = DI/256
    int l0 = blockIdx.y * 8;                         // gridDim.y = LSEQ/8
    float w0 = w[d * DCONV + 0], w1 = w[d * DCONV + 1];
    float w2 = w[d * DCONV + 2], w3 = w[d * DCONV + 3];
    float bb = b[d];
    float x[11];
    #pragma unroll
    for (int t = 0; t < 11; t++) {
        int ll = l0 - 3 + t;
        x[t] = (ll >= 0 && ll < LSEQ) ? g_xz[(size_t)ll * DXZ + d] : 0.f;
    }
    #pragma unroll
    for (int j = 0; j < 8; j++) {
        float s = bb;
        s = fmaf(w0, x[j + 0], s);
        s = fmaf(w1, x[j + 1], s);
        s = fmaf(w2, x[j + 2], s);
        s = fmaf(w3, x[j + 3], s);
        float sig = 1.f / (1.f + __expf(-s));
        float v = s * sig;
        size_t idx = (size_t)(l0 + j) * DI + d;
        g_xr[idx] = v;
        g_xrh[idx] = __float2half(v);
    }
}

// ---------------- chunked selective scan (power-chain exp) ----------------
__global__ void scan_phaseA_kernel(const float* __restrict__ A_log) {
    int d = blockIdx.x * blockDim.x + threadIdx.x;
    int chunk = blockIdx.y;
    __shared__ float sB[CLEN][DS];
    int l0 = chunk * CLEN;
    for (int idx = threadIdx.x; idx < CLEN * DS; idx += blockDim.x) {
        int l = idx >> 4, n = idx & 15;
        sB[l][n] = g_xdbl[(size_t)(l0 + l) * XDBL + DTR + n];
    }
    __syncthreads();

    float Arow[DS], h[DS], P[DS];
    bool chain = true;
    #pragma unroll
    for (int n = 0; n < DS; n++) {
        Arow[n] = -__expf(A_log[(size_t)d * DS + n]);
        h[n] = 0.f; P[n] = 1.f;
    }
    float r0 = Arow[0];
    #pragma unroll
    for (int n = 1; n < DS; n++)
        chain = chain && (fabsf(Arow[n] - (float)(n + 1) * r0)
                          <= 1e-5f * fabsf(Arow[n]) + 1e-7f);

    if (chain) {
        for (int l = 0; l < CLEN; l++) {
            float dl = g_delta[(size_t)(l0 + l) * DI + d];
            float du = dl * g_xr[(size_t)(l0 + l) * DI + d];
            float q = __expf(dl * r0);
            float a = 1.f;
            #pragma unroll
            for (int n = 0; n < DS; n++) {
                a *= q;
                h[n] = fmaf(a, h[n], du * sB[l][n]);
                P[n] *= a;
            }
        }
    } else {
        for (int l = 0; l < CLEN; l++) {
            float dl = g_delta[(size_t)(l0 + l) * DI + d];
            float du = dl * g_xr[(size_t)(l0 + l) * DI + d];
            #pragma unroll
            for (int n = 0; n < DS; n++) {
                float a = __expf(dl * Arow[n]);
                h[n] = fmaf(a, h[n], du * sB[l][n]);
                P[n] *= a;
            }
        }
    }
    size_t base = ((size_t)chunk * DI + d) * DS;
    #pragma unroll
    for (int n = 0; n < DS; n++) {
        g_Aprod[base + n] = P[n];
        g_Hend [base + n] = h[n];
    }
}

__global__ void scan_phaseB_kernel() {
    int i = blockIdx.x * blockDim.x + threadIdx.x;
    if (i >= DI * DS) return;
    float run = 0.f;
    #pragma unroll 8
    for (int c = 0; c < NCH; c++) {
        size_t idx = (size_t)c * DI * DS + i;
        g_Hinit[idx] = run;
        run = fmaf(g_Aprod[idx], run, g_Hend[idx]);
    }
}

__global__ void scan_phaseC_kernel(const float* __restrict__ A_log,
                                   const float* __restrict__ Dp) {
    int d = blockIdx.x * blockDim.x + threadIdx.x;
    int chunk = blockIdx.y;
    __shared__ float sB[CLEN][DS];
    __shared__ float sC[CLEN][DS];
    int l0 = chunk * CLEN;
    for (int idx = threadIdx.x; idx < CLEN * DS; idx += blockDim.x) {
        int l = idx >> 4, n = idx & 15;
        sB[l][n] = g_xdbl[(size_t)(l0 + l) * XDBL + DTR + n];
        sC[l][n] = g_xdbl[(size_t)(l0 + l) * XDBL + DTR + DS + n];
    }
    __syncthreads();

    float Arow[DS], h[DS];
    bool chain = true;
    size_t base = ((size_t)chunk * DI + d) * DS;
    #pragma unroll
    for (int n = 0; n < DS; n++) {
        Arow[n] = -__expf(A_log[(size_t)d * DS + n]);
        h[n] = g_Hinit[base + n];
    }
    float r0 = Arow[0];
    #pragma unroll
    for (int n = 1; n < DS; n++)
        chain = chain && (fabsf(Arow[n] - (float)(n + 1) * r0)
                          <= 1e-5f * fabsf(Arow[n]) + 1e-7f);
    float Dd = Dp[d];

    for (int l = 0; l < CLEN; l++) {
        float dl = g_delta[(size_t)(l0 + l) * DI + d];
        float u  = g_xr[(size_t)(l0 + l) * DI + d];
        float du = dl * u;
        float y = 0.f;
        if (chain) {
            float q = __expf(dl * r0);
            float a = 1.f;
            #pragma unroll
            for (int n = 0; n < DS; n++) {
                a *= q;
                h[n] = fmaf(a, h[n], du * sB[l][n]);
                y = fmaf(h[n], sC[l][n], y);
            }
        } else {
            #pragma unroll
            for (int n = 0; n < DS; n++) {
                float a = __expf(dl * Arow[n]);
                h[n] = fmaf(a, h[n], du * sB[l][n]);
                y = fmaf(h[n], sC[l][n], y);
            }
        }
        y = fmaf(u, Dd, y);
        float res = g_xz[(size_t)(l0 + l) * DXZ + DI + d];
        float sig = 1.f / (1.f + __expf(-res));
        g_ya[(size_t)(l0 + l) * DI + d] = __float2half(y * (res * sig));
    }
}

// ---------------- launcher ----------------
extern "C" void kernel_launch(void* const* d_in, const int* in_sizes, int n_in,
                              void* d_out, int out_size) {
    const int*   ids        = (const int*)  d_in[0];
    const float* emb        = (const float*)d_in[1];
    const float* norm_w     = (const float*)d_in[2];
    const float* in_proj_w  = (const float*)d_in[3];
    const float* conv_w     = (const float*)d_in[4];
    const float* conv_b     = (const float*)d_in[5];
    const float* x_proj_w   = (const float*)d_in[6];
    const float* dt_proj_w  = (const float*)d_in[7];
    const float* dt_proj_b  = (const float*)d_in[8];
    const float* A_log      = (const float*)d_in[9];
    const float* Dp         = (const float*)d_in[10];
    const float* out_proj_w = (const float*)d_in[11];
    float* out = (float*)d_out;

    cudaFuncSetAttribute(gemm_fp16_kernel<0>,
                         cudaFuncAttributeMaxDynamicSharedMemorySize, SMEM_MMA);
    cudaFuncSetAttribute(gemm_fp16_kernel<1>,
                         cudaFuncAttributeMaxDynamicSharedMemorySize, SMEM_MMA);

    // resolve device-global scratch pointers
    __half *xn, *xrh, *ya, *dt, *wt, *wxp, *wdt;
    float *xz, *x_res, *part, *delta;
    cudaGetSymbolAddress((void**)&xn,    g_xn);
    cudaGetSymbolAddress((void**)&xrh,   g_xrh);
    cudaGetSymbolAddress((void**)&ya,    g_ya);
    cudaGetSymbolAddress((void**)&dt,    g_dt);
    cudaGetSymbolAddress((void**)&wt,    g_wt);
    cudaGetSymbolAddress((void**)&wxp,   g_wxp);
    cudaGetSymbolAddress((void**)&wdt,   g_wdt);
    cudaGetSymbolAddress((void**)&xz,    g_xz);
    cudaGetSymbolAddress((void**)&x_res, g_x);
    cudaGetSymbolAddress((void**)&part,  g_part);
    cudaGetSymbolAddress((void**)&delta, g_delta);

    embed_rms_kernel<<<LSEQ, 256>>>(ids, emb, norm_w);   // norm_w[0]

    for (int layer = 0; layer < NLAYER; layer++) {
        // in_proj: [2048,768] @ [768,3072]
        wconv_kernel<<<dim3(DM / 32, DXZ / 32), dim3(32, 8)>>>(
            in_proj_w + (size_t)layer * DM * DXZ, wt, DM, DM, DXZ, DXZ);
        gemm_fp16_kernel<0><<<dim3(DXZ / 128, LSEQ / 128, 1), 256, SMEM_MMA>>>(
            xn, wt, xz, nullptr, DM, DM, DXZ, DXZ);

        // dt_proj weights convert early (independent)
        wconv_kernel<<<dim3(64 / 32, DI / 32), dim3(32, 8)>>>(
            dt_proj_w + (size_t)layer * DTR * DI, wdt, DTR, 64, DI, DI);

        conv_silu_kernel<<<dim3(DI / 256, LSEQ / 8), 256>>>(
            conv_w + (size_t)layer * DI * DCONV,
            conv_b + (size_t)layer * DI);

        // x_proj: [2048,1536] @ [1536,80] via split-K 8 + reduce
        wconv_kernel<<<dim3(DI / 32, 128 / 32), dim3(32, 8)>>>(
            x_proj_w + (size_t)layer * DI * XDBL, wxp, DI, DI, XDBL, 128);
        gemm_fp16_kernel<0><<<dim3(1, LSEQ / 128, 8), 256, SMEM_MMA>>>(
            xrh, wxp, part, nullptr, DI, DI / 8, XDBL, XDBL);
        xproj_reduce_kernel<<<(LSEQ * XDBL + 255) / 256, 256>>>();

        // dt_proj: [2048,64pad] @ [64pad,1536], softplus+bias epilogue
        gemm_fp16_kernel<1><<<dim3(DI / 128, LSEQ / 128, 1), 256, SMEM_MMA>>>(
            dt, wdt, delta, dt_proj_b + (size_t)layer * DI, 64, 64, DI, DI);

        scan_phaseA_kernel<<<dim3(DI / 128, NCH), 128>>>(
            A_log + (size_t)layer * DI * DS);
        scan_phaseB_kernel<<<(DI * DS + 255) / 256, 256>>>();
        scan_phaseC_kernel<<<dim3(DI / 128, NCH), 128>>>(
            A_log + (size_t)layer * DI * DS,
            Dp + (size_t)layer * DI);

        // out_proj: [2048,1536] @ [1536,768] via split-K 3 + fused reduce/rms
        wconv_kernel<<<dim3(DI / 32, DM / 32), dim3(32, 8)>>>(
            out_proj_w + (size_t)layer * DI * DM, wt, DI, DI, DM, DM);
        gemm_fp16_kernel<0><<<dim3(DM / 128, LSEQ / 128, 3), 256, SMEM_MMA>>>(
            ya, wt, part, nullptr, DI, DI / 3, DM, DM);

        if (layer == NLAYER - 1) {
            outred_rms_kernel<<<LSEQ, 256>>>(nullptr, out, 0);
        } else {
            outred_rms_kernel<<<LSEQ, 256>>>(norm_w + (size_t)(layer + 1) * DM,
                                             x_res, 1);
        }
    }
}

// round 9
// speedup vs baseline: 5.0134x; 1.0458x over previous
#include <cuda_runtime.h>
#include <cuda_fp16.h>
#include <math.h>
#include <stdint.h>

// ---------------- problem constants ----------------
#define LSEQ   2048
#define DM     768
#define DI     1536          // 2*DM
#define DXZ    3072          // 2*DI
#define DTR    48
#define DS     16
#define DCONV  4
#define NLAYER 2
#define XDBL   80            // DTR + 2*DS
#define NCH    64
#define CLEN   32            // LSEQ / NCH

// ---------------- scratch (device globals, no allocation) ----------------
__device__ __align__(16) float g_x   [LSEQ * DM];    // residual stream
__device__ __align__(16) float g_xz  [LSEQ * DXZ];   // in_proj output (xr | res)
__device__ __align__(16) float g_xr  [LSEQ * DI];    // conv+silu output (fp32 for scan)
__device__ __align__(16) float g_xdbl[LSEQ * XDBL];  // x_proj output (dt | B | C)
__device__ __align__(16) float g_delta[LSEQ * DI];   // softplus(dt@dt_proj + b)
__device__ __align__(16) float g_Aprod[NCH * DI * DS];
__device__ __align__(16) float g_Hend [NCH * DI * DS];
__device__ __align__(16) float g_Hinit[NCH * DI * DS];

// fp16 activations for tensor-core GEMMs
__device__ __align__(16) __half g_xn [LSEQ * DM];
__device__ __align__(16) __half g_xrh[LSEQ * DI];
__device__ __align__(16) __half g_ya [LSEQ * DI];
__device__ __align__(16) __half g_dt [LSEQ * 64];     // dt cols padded 48->64
// fp16 weights, transposed [N][K], per-layer buffers (prepared once at start)
__device__ __align__(16) __half g_win [NLAYER * DM * DXZ];
__device__ __align__(16) __half g_wout[NLAYER * DI * DM];
__device__ __align__(16) __half g_wxp [NLAYER * 128 * DI];
__device__ __align__(16) __half g_wdt [NLAYER * DI * 64];
// split-K partials
__device__ __align__(16) float g_part[3 * LSEQ * DM];

// ---------------- small helpers ----------------
__device__ __forceinline__ uint32_t smem_u32(const void* p) {
    uint32_t a;
    asm("{ .reg .u64 t; cvta.to.shared.u64 t, %1; cvt.u32.u64 %0, t; }"
        : "=r"(a) : "l"(p));
    return a;
}
__device__ __forceinline__ void ldm4(uint32_t addr, uint32_t r[4]) {
    asm volatile("ldmatrix.sync.aligned.m8n8.x4.shared.b16 {%0,%1,%2,%3}, [%4];"
                 : "=r"(r[0]), "=r"(r[1]), "=r"(r[2]), "=r"(r[3]) : "r"(addr));
}
__device__ __forceinline__ void mma16816(float c[4], const uint32_t a[4],
                                         const uint32_t b0, const uint32_t b1) {
    asm volatile(
        "mma.sync.aligned.m16n8k16.row.col.f32.f16.f16.f32 "
        "{%0,%1,%2,%3}, {%4,%5,%6,%7}, {%8,%9}, {%0,%1,%2,%3};"
        : "+f"(c[0]), "+f"(c[1]), "+f"(c[2]), "+f"(c[3])
        : "r"(a[0]), "r"(a[1]), "r"(a[2]), "r"(a[3]), "r"(b0), "r"(b1));
}

// ---------------- single-term fp16 GEMM via mma.sync ----------------
// C[2048,N] = A[2048,K] @ B^T with B as [N][K] row-major fp16.
// Tile 128x128, K-slab 64, 3 stages x 2 tiles (110.6KB), 2 CTAs/SM,
// fragment-first mainloop per 32-half, 1 sync per 64-K slab.
#define SROW    72                       // 64 halfs + 8 pad (144B row stride)
#define TILE_E  (128 * SROW)             // 9216 halfs = 18432 B
#define NSTAGE  3
#define SMEM_MMA (NSTAGE * 2 * TILE_E * 2)   // 110592 B

__device__ __forceinline__ void mma_load_stage(
        uint32_t smb, int stage,
        const __half* __restrict__ A, const __half* __restrict__ B,
        int row0, int col0, int k0, int K, int tid) {
    #pragma unroll
    for (int t = 0; t < 2; t++) {
        const __half* src = (t == 0) ? A : B;
        int r0 = (t == 0) ? row0 : col0;
        #pragma unroll
        for (int i = 0; i < 4; i++) {
            int c = tid + i * 256;
            int row = c >> 3, kc = (c & 7) * 8;
            uint32_t dst = smb + (uint32_t)(((stage * 2 + t) * TILE_E) + row * SROW + kc) * 2u;
            const void* gsrc = src + (size_t)(r0 + row) * K + k0 + kc;
            asm volatile("cp.async.cg.shared.global [%0], [%1], 16;"
                         :: "r"(dst), "l"(gsrc));
        }
    }
    asm volatile("cp.async.commit_group;" ::: "memory");
}

// MODE 0: plain write   MODE 1: softplus(v + bias[n])
template<int MODE>
__global__ void __launch_bounds__(256, 2)
gemm_fp16_kernel(const __half* __restrict__ Ag, const __half* __restrict__ Bg,
                 float* __restrict__ C, const float* __restrict__ bias,
                 int K, int ksize, int ldc, int Nvalid) {
    extern __shared__ __half sm[];
    const int tid = threadIdx.x, lane = tid & 31, wid = tid >> 5;
    const int wm = wid & 3, wn = wid >> 2;         // 4 m-warps x 2 n-warps
    const int row0 = blockIdx.y * 128, col0 = blockIdx.x * 128;
    const int kb = blockIdx.z * ksize;
    C += (size_t)blockIdx.z * LSEQ * ldc;
    uint32_t smb = smem_u32(sm);

    float acc[2][8][4] = {};
    const int S = ksize / 64;

    mma_load_stage(smb, 0, Ag, Bg, row0, col0, kb, K, tid);
    if (S > 1) mma_load_stage(smb, 1, Ag, Bg, row0, col0, kb + 64, K, tid);

    const int lrow = lane & 15, lcol0 = (lane >> 4) * 8;

    for (int s = 0; s < S; s++) {
        if (s + 1 < S) {
            asm volatile("cp.async.wait_group 1;" ::: "memory");
        } else {
            asm volatile("cp.async.wait_group 0;" ::: "memory");
        }
        __syncthreads();
        if (s + 2 < S)
            mma_load_stage(smb, (s + 2) % NSTAGE, Ag, Bg,
                           row0, col0, kb + (s + 2) * 64, K, tid);

        int st = s % NSTAGE;
        uint32_t bA = smb + (uint32_t)((st * 2 + 0) * TILE_E) * 2u;
        uint32_t bB = smb + (uint32_t)((st * 2 + 1) * TILE_E) * 2u;

        #pragma unroll
        for (int kh = 0; kh < 64; kh += 32) {
            // fragment-first per 32-K half: 12 LDSM then 16 MMA
            uint32_t ah[2][2][4];   // [kk2][mt]
            uint32_t bb[2][4][4];   // [kk2][g]
            #pragma unroll
            for (int kk2 = 0; kk2 < 2; kk2++) {
                int kk = kh + kk2 * 16;
                #pragma unroll
                for (int mt = 0; mt < 2; mt++) {
                    uint32_t off = (uint32_t)((wm * 32 + mt * 16 + lrow) * SROW + kk + lcol0) * 2u;
                    ldm4(bA + off, ah[kk2][mt]);
                }
                #pragma unroll
                for (int g = 0; g < 4; g++) {
                    uint32_t off = (uint32_t)((wn * 64 + g * 16 + lrow) * SROW + kk + lcol0) * 2u;
                    ldm4(bB + off, bb[kk2][g]);
                }
            }
            #pragma unroll
            for (int kk2 = 0; kk2 < 2; kk2++) {
                #pragma unroll
                for (int g = 0; g < 4; g++) {
                    #pragma unroll
                    for (int mt = 0; mt < 2; mt++) {
                        mma16816(acc[mt][2 * g + 0], ah[kk2][mt], bb[kk2][g][0], bb[kk2][g][2]);
                        mma16816(acc[mt][2 * g + 1], ah[kk2][mt], bb[kk2][g][1], bb[kk2][g][3]);
                    }
                }
            }
        }
    }

    // epilogue
    int gq = lane >> 2, tq = lane & 3;
    #pragma unroll
    for (int mt = 0; mt < 2; mt++) {
        #pragma unroll
        for (int n8 = 0; n8 < 8; n8++) {
            int rm = row0 + wm * 32 + mt * 16 + gq;
            int cn = col0 + wn * 64 + n8 * 8 + 2 * tq;
            if (cn >= Nvalid) continue;
            float v[4] = {acc[mt][n8][0], acc[mt][n8][1],
                          acc[mt][n8][2], acc[mt][n8][3]};
            if (MODE == 1) {
                float b0 = bias[cn], b1 = bias[cn + 1];
                v[0] += b0; v[1] += b1; v[2] += b0; v[3] += b1;
                #pragma unroll
                for (int q = 0; q < 4; q++)
                    v[q] = (v[q] > 20.f) ? v[q] : log1pf(__expf(v[q]));
            }
            *reinterpret_cast<float2*>(C + (size_t)rm * ldc + cn) =
                make_float2(v[0], v[1]);
            *reinterpret_cast<float2*>(C + (size_t)(rm + 8) * ldc + cn) =
                make_float2(v[2], v[3]);
        }
    }
}

// reduce 8 x_proj split-K partials -> g_xdbl, emit fp16 dt cols (pad 64)
__global__ void xproj_reduce_kernel() {
    int i = blockIdx.x * blockDim.x + threadIdx.x;
    if (i >= LSEQ * XDBL) return;
    float s = 0.f;
    #pragma unroll
    for (int z = 0; z < 8; z++) s += g_part[(size_t)z * LSEQ * XDBL + i];
    g_xdbl[i] = s;
    int l = i / XDBL, c = i - l * XDBL;
    if (c < 64) g_dt[(size_t)l * 64 + c] = __float2half(s);
}

// ---------------- fused residual-reduce + rmsnorm ----------------
__global__ void outred_rms_kernel(const float* __restrict__ norm_w,
                                  float* __restrict__ dest, int do_norm) {
    int l = blockIdx.x;
    float v[3];
    float s = 0.f;
    #pragma unroll
    for (int i = 0; i < 3; i++) {
        int d = threadIdx.x + i * 256;
        size_t idx = (size_t)l * DM + d;
        float t = g_x[idx];
        #pragma unroll
        for (int z = 0; z < 3; z++) t += g_part[(size_t)z * LSEQ * DM + idx];
        dest[idx] = t;
        v[i] = t;
        s += t * t;
    }
    if (!do_norm) return;
    __shared__ float red[8];
    #pragma unroll
    for (int o = 16; o; o >>= 1) s += __shfl_xor_sync(0xffffffffu, s, o);
    if ((threadIdx.x & 31) == 0) red[threadIdx.x >> 5] = s;
    __syncthreads();
    if (threadIdx.x < 8) {
        float t = red[threadIdx.x];
        #pragma unroll
        for (int o = 4; o; o >>= 1) t += __shfl_xor_sync(0xffu, t, o);
        if (threadIdx.x == 0) red[0] = rsqrtf(t / (float)DM + 1e-5f);
    }
    __syncthreads();
    float rinv = red[0];
    #pragma unroll
    for (int i = 0; i < 3; i++) {
        int d = threadIdx.x + i * 256;
        g_xn[(size_t)l * DM + d] = __float2half(v[i] * rinv * norm_w[d]);
    }
}

// ---------------- fused embed + rmsnorm (layer 0 entry) ----------------
__global__ void embed_rms_kernel(const int* __restrict__ ids,
                                 const float* __restrict__ emb,
                                 const float* __restrict__ norm_w) {
    int l = blockIdx.x;
    const float* erow = emb + (size_t)ids[l] * DM;
    float v[3];
    float s = 0.f;
    #pragma unroll
    for (int i = 0; i < 3; i++) {
        int d = threadIdx.x + i * 256;
        float t = erow[d];
        g_x[(size_t)l * DM + d] = t;
        v[i] = t;
        s += t * t;
    }
    __shared__ float red[8];
    #pragma unroll
    for (int o = 16; o; o >>= 1) s += __shfl_xor_sync(0xffffffffu, s, o);
    if ((threadIdx.x & 31) == 0) red[threadIdx.x >> 5] = s;
    __syncthreads();
    if (threadIdx.x < 8) {
        float t = red[threadIdx.x];
        #pragma unroll
        for (int o = 4; o; o >>= 1) t += __shfl_xor_sync(0xffu, t, o);
        if (threadIdx.x == 0) red[0] = rsqrtf(t / (float)DM + 1e-5f);
    }
    __syncthreads();
    float rinv = red[0];
    #pragma unroll
    for (int i = 0; i < 3; i++) {
        int d = threadIdx.x + i * 256;
        g_xn[(size_t)l * DM + d] = __float2half(v[i] * rinv * norm_w[d]);
    }
}

// ---------------- fused weight prep: ALL transposes, both layers, 1 kernel ----------------
// tile counts per layer (32x32 tiles):
//   in : kt 24 x nt 96 = 2304     out: kt 48 x nt 24 = 1152
//   xp : kt 48 x nt 4  = 192      dt : kt 2  x nt 48 = 96
#define WP_TIN  2304
#define WP_TOUT 1152
#define WP_TXP  192
#define WP_TDT  96
#define WP_PER_LAYER (WP_TIN + WP_TOUT + WP_TXP + WP_TDT)   // 3744

__device__ __forceinline__ void wp_tile(const float* __restrict__ W,
                                        __half* __restrict__ out,
                                        int Kin, int Kpad, int N, int Npad,
                                        int k0, int n0) {
    __shared__ float t[32][33];
    #pragma unroll
    for (int i = 0; i < 4; i++) {
        int k = k0 + threadIdx.y + i * 8;
        int n = n0 + threadIdx.x;
        t[threadIdx.y + i * 8][threadIdx.x] =
            (k < Kin && n < N) ? W[(size_t)k * N + n] : 0.f;
    }
    __syncthreads();
    #pragma unroll
    for (int i = 0; i < 4; i++) {
        int n = n0 + threadIdx.y + i * 8;
        int k = k0 + threadIdx.x;
        if (n < Npad && k < Kpad)
            out[(size_t)n * Kpad + k] = __float2half(t[threadIdx.x][threadIdx.y + i * 8]);
    }
}

__global__ void wprep_kernel(const float* __restrict__ in_proj_w,
                             const float* __restrict__ out_proj_w,
                             const float* __restrict__ x_proj_w,
                             const float* __restrict__ dt_proj_w) {
    int layer = blockIdx.y;
    int b = blockIdx.x;
    if (b < WP_TIN) {
        int kt = b % 24, nt = b / 24;
        wp_tile(in_proj_w + (size_t)layer * DM * DXZ,
                g_win + (size_t)layer * DM * DXZ,
                DM, DM, DXZ, DXZ, kt * 32, nt * 32);
        return;
    }
    b -= WP_TIN;
    if (b < WP_TOUT) {
        int kt = b % 48, nt = b / 48;
        wp_tile(out_proj_w + (size_t)layer * DI * DM,
                g_wout + (size_t)layer * DI * DM,
                DI, DI, DM, DM, kt * 32, nt * 32);
        return;
    }
    b -= WP_TOUT;
    if (b < WP_TXP) {
        int kt = b % 48, nt = b / 48;
        wp_tile(x_proj_w + (size_t)layer * DI * XDBL,
                g_wxp + (size_t)layer * 128 * DI,
                DI, DI, XDBL, 128, kt * 32, nt * 32);
        return;
    }
    b -= WP_TXP;
    {
        int kt = b % 2, nt = b / 2;
        wp_tile(dt_proj_w + (size_t)layer * DTR * DI,
                g_wdt + (size_t)layer * DI * 64,
                DTR, 64, DI, DI, kt * 32, nt * 32);
    }
}

// conv + silu: 8 outputs along l per thread, taps reused in registers
__global__ void conv_silu_kernel(const float* __restrict__ w,
                                 const float* __restrict__ b) {
    int d = blockIdx.x * 256 + threadIdx.x;          // gridDim.x = DI/256
    int l0 = blockIdx.y * 8;                         // gridDim.y = LSEQ/8
    float w0 = w[d * DCONV + 0], w1 = w[d * DCONV + 1];
    float w2 = w[d * DCONV + 2], w3 = w[d * DCONV + 3];
    float bb = b[d];
    float x[11];
    #pragma unroll
    for (int t = 0; t < 11; t++) {
        int ll = l0 - 3 + t;
        x[t] = (ll >= 0 && ll < LSEQ) ? g_xz[(size_t)ll * DXZ + d] : 0.f;
    }
    #pragma unroll
    for (int j = 0; j < 8; j++) {
        float s = bb;
        s = fmaf(w0, x[j + 0], s);
        s = fmaf(w1, x[j + 1], s);
        s = fmaf(w2, x[j + 2], s);
        s = fmaf(w3, x[j + 3], s);
        float sig = 1.f / (1.f + __expf(-s));
        float v = s * sig;
        size_t idx = (size_t)(l0 + j) * DI + d;
        g_xr[idx] = v;
        g_xrh[idx] = __float2half(v);
    }
}

// ---------------- chunked selective scan (power-chain exp) ----------------
__global__ void scan_phaseA_kernel(const float* __restrict__ A_log) {
    int d = blockIdx.x * blockDim.x + threadIdx.x;
    int chunk = blockIdx.y;
    __shared__ float sB[CLEN][DS];
    int l0 = chunk * CLEN;
    for (int idx = threadIdx.x; idx < CLEN * DS; idx += blockDim.x) {
        int l = idx >> 4, n = idx & 15;
        sB[l][n] = g_xdbl[(size_t)(l0 + l) * XDBL + DTR + n];
    }
    __syncthreads();

    float Arow[DS], h[DS], P[DS];
    bool chain = true;
    #pragma unroll
    for (int n = 0; n < DS; n++) {
        Arow[n] = -__expf(A_log[(size_t)d * DS + n]);
        h[n] = 0.f; P[n] = 1.f;
    }
    float r0 = Arow[0];
    #pragma unroll
    for (int n = 1; n < DS; n++)
        chain = chain && (fabsf(Arow[n] - (float)(n + 1) * r0)
                          <= 1e-5f * fabsf(Arow[n]) + 1e-7f);

    if (chain) {
        for (int l = 0; l < CLEN; l++) {
            float dl = g_delta[(size_t)(l0 + l) * DI + d];
            float du = dl * g_xr[(size_t)(l0 + l) * DI + d];
            float q = __expf(dl * r0);
            float a = 1.f;
            #pragma unroll
            for (int n = 0; n < DS; n++) {
                a *= q;
                h[n] = fmaf(a, h[n], du * sB[l][n]);
                P[n] *= a;
            }
        }
    } else {
        for (int l = 0; l < CLEN; l++) {
            float dl = g_delta[(size_t)(l0 + l) * DI + d];
            float du = dl * g_xr[(size_t)(l0 + l) * DI + d];
            #pragma unroll
            for (int n = 0; n < DS; n++) {
                float a = __expf(dl * Arow[n]);
                h[n] = fmaf(a, h[n], du * sB[l][n]);
                P[n] *= a;
            }
        }
    }
    size_t base = ((size_t)chunk * DI + d) * DS;
    #pragma unroll
    for (int n = 0; n < DS; n++) {
        g_Aprod[base + n] = P[n];
        g_Hend [base + n] = h[n];
    }
}

__global__ void scan_phaseB_kernel() {
    int i = blockIdx.x * blockDim.x + threadIdx.x;
    if (i >= DI * DS) return;
    float run = 0.f;
    #pragma unroll 8
    for (int c = 0; c < NCH; c++) {
        size_t idx = (size_t)c * DI * DS + i;
        g_Hinit[idx] = run;
        run = fmaf(g_Aprod[idx], run, g_Hend[idx]);
    }
}

__global__ void scan_phaseC_kernel(const float* __restrict__ A_log,
                                   const float* __restrict__ Dp) {
    int d = blockIdx.x * blockDim.x + threadIdx.x;
    int chunk = blockIdx.y;
    __shared__ float sB[CLEN][DS];
    __shared__ float sC[CLEN][DS];
    int l0 = chunk * CLEN;
    for (int idx = threadIdx.x; idx < CLEN * DS; idx += blockDim.x) {
        int l = idx >> 4, n = idx & 15;
        sB[l][n] = g_xdbl[(size_t)(l0 + l) * XDBL + DTR + n];
        sC[l][n] = g_xdbl[(size_t)(l0 + l) * XDBL + DTR + DS + n];
    }
    __syncthreads();

    float Arow[DS], h[DS];
    bool chain = true;
    size_t base = ((size_t)chunk * DI + d) * DS;
    #pragma unroll
    for (int n = 0; n < DS; n++) {
        Arow[n] = -__expf(A_log[(size_t)d * DS + n]);
        h[n] = g_Hinit[base + n];
    }
    float r0 = Arow[0];
    #pragma unroll
    for (int n = 1; n < DS; n++)
        chain = chain && (fabsf(Arow[n] - (float)(n + 1) * r0)
                          <= 1e-5f * fabsf(Arow[n]) + 1e-7f);
    float Dd = Dp[d];

    for (int l = 0; l < CLEN; l++) {
        float dl = g_delta[(size_t)(l0 + l) * DI + d];
        float u  = g_xr[(size_t)(l0 + l) * DI + d];
        float du = dl * u;
        float y = 0.f;
        if (chain) {
            float q = __expf(dl * r0);
            float a = 1.f;
            #pragma unroll
            for (int n = 0; n < DS; n++) {
                a *= q;
                h[n] = fmaf(a, h[n], du * sB[l][n]);
                y = fmaf(h[n], sC[l][n], y);
            }
        } else {
            #pragma unroll
            for (int n = 0; n < DS; n++) {
                float a = __expf(dl * Arow[n]);
                h[n] = fmaf(a, h[n], du * sB[l][n]);
                y = fmaf(h[n], sC[l][n], y);
            }
        }
        y = fmaf(u, Dd, y);
        float res = g_xz[(size_t)(l0 + l) * DXZ + DI + d];
        float sig = 1.f / (1.f + __expf(-res));
        g_ya[(size_t)(l0 + l) * DI + d] = __float2half(y * (res * sig));
    }
}

// ---------------- launcher ----------------
extern "C" void kernel_launch(void* const* d_in, const int* in_sizes, int n_in,
                              void* d_out, int out_size) {
    const int*   ids        = (const int*)  d_in[0];
    const float* emb        = (const float*)d_in[1];
    const float* norm_w     = (const float*)d_in[2];
    const float* in_proj_w  = (const float*)d_in[3];
    const float* conv_w     = (const float*)d_in[4];
    const float* conv_b     = (const float*)d_in[5];
    const float* x_proj_w   = (const float*)d_in[6];
    const float* dt_proj_w  = (const float*)d_in[7];
    const float* dt_proj_b  = (const float*)d_in[8];
    const float* A_log      = (const float*)d_in[9];
    const float* Dp         = (const float*)d_in[10];
    const float* out_proj_w = (const float*)d_in[11];
    float* out = (float*)d_out;

    cudaFuncSetAttribute(gemm_fp16_kernel<0>,
                         cudaFuncAttributeMaxDynamicSharedMemorySize, SMEM_MMA);
    cudaFuncSetAttribute(gemm_fp16_kernel<1>,
                         cudaFuncAttributeMaxDynamicSharedMemorySize, SMEM_MMA);

    // resolve device-global scratch pointers
    __half *xn, *xrh, *ya, *dt, *win, *wout, *wxp, *wdt;
    float *xz, *x_res, *part, *delta;
    cudaGetSymbolAddress((void**)&xn,    g_xn);
    cudaGetSymbolAddress((void**)&xrh,   g_xrh);
    cudaGetSymbolAddress((void**)&ya,    g_ya);
    cudaGetSymbolAddress((void**)&dt,    g_dt);
    cudaGetSymbolAddress((void**)&win,   g_win);
    cudaGetSymbolAddress((void**)&wout,  g_wout);
    cudaGetSymbolAddress((void**)&wxp,   g_wxp);
    cudaGetSymbolAddress((void**)&wdt,   g_wdt);
    cudaGetSymbolAddress((void**)&xz,    g_xz);
    cudaGetSymbolAddress((void**)&x_res, g_x);
    cudaGetSymbolAddress((void**)&part,  g_part);
    cudaGetSymbolAddress((void**)&delta, g_delta);

    // ALL weight transposes up front, one kernel
    wprep_kernel<<<dim3(WP_PER_LAYER, NLAYER), dim3(32, 8)>>>(
        in_proj_w, out_proj_w, x_proj_w, dt_proj_w);

    embed_rms_kernel<<<LSEQ, 256>>>(ids, emb, norm_w);   // norm_w[0]

    for (int layer = 0; layer < NLAYER; layer++) {
        const __half* wt_in  = win  + (size_t)layer * DM * DXZ;
        const __half* wt_out = wout + (size_t)layer * DI * DM;
        const __half* wt_xp  = wxp  + (size_t)layer * 128 * DI;
        const __half* wt_dt  = wdt  + (size_t)layer * DI * 64;

        // in_proj: [2048,768] @ [768,3072]
        gemm_fp16_kernel<0><<<dim3(DXZ / 128, LSEQ / 128, 1), 256, SMEM_MMA>>>(
            xn, wt_in, xz, nullptr, DM, DM, DXZ, DXZ);

        conv_silu_kernel<<<dim3(DI / 256, LSEQ / 8), 256>>>(
            conv_w + (size_t)layer * DI * DCONV,
            conv_b + (size_t)layer * DI);

        // x_proj: [2048,1536] @ [1536,80] via split-K 8 + reduce
        gemm_fp16_kernel<0><<<dim3(1, LSEQ / 128, 8), 256, SMEM_MMA>>>(
            xrh, wt_xp, part, nullptr, DI, DI / 8, XDBL, XDBL);
        xproj_reduce_kernel<<<(LSEQ * XDBL + 255) / 256, 256>>>();

        // dt_proj: [2048,64pad] @ [64pad,1536], softplus+bias epilogue
        gemm_fp16_kernel<1><<<dim3(DI / 128, LSEQ / 128, 1), 256, SMEM_MMA>>>(
            dt, wt_dt, delta, dt_proj_b + (size_t)layer * DI, 64, 64, DI, DI);

        scan_phaseA_kernel<<<dim3(DI / 128, NCH), 128>>>(
            A_log + (size_t)layer * DI * DS);
        scan_phaseB_kernel<<<(DI * DS + 255) / 256, 256>>>();
        scan_phaseC_kernel<<<dim3(DI / 128, NCH), 128>>>(
            A_log + (size_t)layer * DI * DS,
            Dp + (size_t)layer * DI);

        // out_proj: [2048,1536] @ [1536,768] via split-K 3 + fused reduce/rms
        gemm_fp16_kernel<0><<<dim3(DM / 128, LSEQ / 128, 3), 256, SMEM_MMA>>>(
            ya, wt_out, part, nullptr, DI, DI / 3, DM, DM);

        if (layer == NLAYER - 1) {
            outred_rms_kernel<<<LSEQ, 256>>>(nullptr, out, 0);
        } else {
            outred_rms_kernel<<<LSEQ, 256>>>(norm_w + (size_t)(layer + 1) * DM,
                                             x_res, 1);
        }
    }
}